// round 14
// baseline (speedup 1.0000x reference)
#include <cuda_runtime.h>
#include <mma.h>
#include <math.h>
#include <cstdint>
#include <cuda_bf16.h>

using namespace nvcuda;

#define NN 50000
#define NE 150000
#define NG 2000
#define DD 75
#define TW 5
#define FO 15
#define NL 4
#define AVGLOG 1.1308269950720914f
#define CLD 828   // CAB row stride (multiple of 4 for wmma direct store)

typedef __nv_bfloat16 bf16;

// ---------------- scratch (device globals; no allocs) ----------------
__device__ __align__(256) bf16  g_Hh[NN * 80];
__device__ __align__(256) bf16  g_Hl[NN * 80];
__device__ __align__(256) float g_CAB[NN * CLD];     // fp32: [A(375) | B(375) | H@W0(75) | pad]
__device__ __align__(256) bf16  g_AGGh[NN * 1520];   // [N][T][304] padded towers
__device__ __align__(256) bf16  g_AGGl[NN * 1520];
__device__ __align__(256) bf16  g_Zh[NN * 80];
__device__ __align__(256) bf16  g_Zl[NN * 80];
__device__ float g_Y[NN * DD];
__device__ float g_amp[NN];
__device__ float g_invamp[NN];
__device__ int   g_deg[NN * 2];
__device__ int   g_rowptr[NN + 1];
__device__ int   g_csr[NE];
__device__ int   g_bsum[256];
__device__ int   g_boffs[256];
__device__ __align__(256) bf16  g_Wcath[NL * 75 * 832];
__device__ __align__(256) bf16  g_Wcatl[NL * 75 * 832];
__device__ float g_Etab[NL * 4 * 375];
__device__ __align__(256) bf16  g_WGh[NL * TW * 300 * 48];
__device__ __align__(256) bf16  g_WGl[NL * TW * 300 * 48];
__device__ __align__(256) bf16  g_Wlinh[NL * 75 * 80];
__device__ __align__(256) bf16  g_Wlinl[NL * 75 * 80];
__device__ double g_bnS[NL * DD];
__device__ double g_bnQ[NL * DD];
__device__ float g_pool[NG * DD];
__device__ float g_z1[NG * 50];
__device__ float g_z2[NG * 25];

__device__ __forceinline__ void bsplit(float v, bf16* h, bf16* l) {
    bf16 hi = __float2bfloat16(v);
    *h = hi;
    *l = __float2bfloat16(v - __bfloat162float(hi));
}

// ---------------- cp.async helpers ----------------
__device__ __forceinline__ void cp16(unsigned dst, const void* src, bool pred) {
    int sz = pred ? 16 : 0;   // sz=0 -> zero-fill
    asm volatile("cp.async.cg.shared.global [%0], [%1], 16, %2;\n" ::"r"(dst), "l"(src),
                 "r"(sz));
}
#define CP_COMMIT() asm volatile("cp.async.commit_group;\n" ::: "memory")
#define CP_WAIT1() asm volatile("cp.async.wait_group 1;\n" ::: "memory")
#define CP_WAIT0() asm volatile("cp.async.wait_group 0;\n" ::: "memory")

// ---------------- split-bf16 GEMM; pre-split hi/lo planes; 16B async loads ----------
// tile 128x64, 256 threads, 4 CTAs/SM target. Template MODE keeps per-variant regs tight.
// MODE 0: standard epilogue; MODE 1: PNA combine -> Z planes; MODE 2: Y + BN stats.
#define SAS 24
#define SBS 72
#define SA_PLANE (128 * SAS)
#define SB_PLANE (16 * SBS)
#define SMEM_BYTES (128 * 72 * 4)   // sC (36864) > stages (33792)

template <int MODE>
__global__ __launch_bounds__(256, 4) void tgemm_kernel(
    const bf16* __restrict__ Ah, const bf16* __restrict__ Al, int lda, long sAb,
    const bf16* __restrict__ Bh, const bf16* __restrict__ Bl, int ldb, long sBb,
    float* __restrict__ C, int ldc, long sCb,
    int M, int N, int K,
    const float* __restrict__ bias,
    const float* __restrict__ addC, int ldadd,
    const float* __restrict__ amp, const float* __restrict__ invamp,
    bf16* __restrict__ Zph, bf16* __restrict__ Zpl,
    double* __restrict__ bnS, double* __restrict__ bnQ,
    int act) {
    extern __shared__ char smem_raw[];
    __shared__ float rs[256], rq[256];
    bf16* bb = (bf16*)smem_raw;
    float* sC = (float*)smem_raw;

    const bf16* Abh = Ah + (long)blockIdx.z * sAb;
    const bf16* Abl = Al + (long)blockIdx.z * sAb;
    const bf16* Bbh = Bh + (long)blockIdx.z * sBb;
    const bf16* Bbl = Bl + (long)blockIdx.z * sBb;
    float* Cb = C + (long)blockIdx.z * sCb;
    int m0 = blockIdx.y * 128, n0 = blockIdx.x * 64;
    int tid = threadIdx.x;
    int warp = tid >> 5;
    int wm = (warp & 3) * 32;
    int wn = (warp >> 2) * 32;
    int numK = (K + 15) / 16;

    // ---- precomputed loader state ----
    const bf16* aSrc[2];
    unsigned aDst[2];
    bool aPred[2];
#pragma unroll
    for (int u = 0; u < 2; u++) {
        int idx = tid + u * 256;
        int pl = idx >> 8, rem = idx & 255;
        int r = rem >> 1, ch = rem & 1;
        const bf16* base = pl ? Abl : Abh;
        aPred[u] = (m0 + r) < M;
        aSrc[u] = base + (long)(m0 + r) * lda + ch * 8;
        aDst[u] = (unsigned)__cvta_generic_to_shared(bb + pl * 2 * SA_PLANE + r * SAS + ch * 8);
    }
    int bPl = tid >> 7, bRem = tid & 127;
    int bR = bRem >> 3, bCh = bRem & 7;
    const bf16* bBase = bPl ? Bbl : Bbh;
    bool bPredN = (n0 + bCh * 8) < ldb;
    const bf16* bSrc = bBase + (long)bR * ldb + n0 + bCh * 8;
    unsigned bDst = (unsigned)__cvta_generic_to_shared(bb + 4 * SA_PLANE + bPl * 2 * SB_PLANE +
                                                       bR * SBS + bCh * 8);

    auto load_stage = [&](int st, int k0) {
#pragma unroll
        for (int u = 0; u < 2; u++)
            cp16(aDst[u] + st * SA_PLANE * 2, aPred[u] ? (aSrc[u] + k0) : Abh, aPred[u]);
        bool p = bPredN && (k0 + bR) < K;
        cp16(bDst + st * SB_PLANE * 2, p ? (bSrc + (long)k0 * ldb) : Bbh, p);
    };

    wmma::fragment<wmma::accumulator, 16, 16, 16, float> acc[2][2];
#pragma unroll
    for (int i = 0; i < 2; i++)
#pragma unroll
        for (int j = 0; j < 2; j++) wmma::fill_fragment(acc[i][j], 0.f);

    load_stage(0, 0);
    CP_COMMIT();

    for (int kt = 0; kt < numK; kt++) {
        int st = kt & 1;
        if (kt + 1 < numK) {
            load_stage(st ^ 1, (kt + 1) * 16);
            CP_COMMIT();
            CP_WAIT1();
        } else {
            CP_WAIT0();
        }
        __syncthreads();

        bf16* sAh = bb + st * SA_PLANE;
        bf16* sAl = bb + 2 * SA_PLANE + st * SA_PLANE;
        bf16* sBh = bb + 4 * SA_PLANE + st * SB_PLANE;
        bf16* sBl = bb + 4 * SA_PLANE + 2 * SB_PLANE + st * SB_PLANE;

        wmma::fragment<wmma::matrix_a, 16, 16, 16, bf16, wmma::row_major> ah[2], al[2];
        wmma::fragment<wmma::matrix_b, 16, 16, 16, bf16, wmma::row_major> bh[2], bl[2];
#pragma unroll
        for (int i = 0; i < 2; i++) {
            wmma::load_matrix_sync(ah[i], &sAh[(wm + 16 * i) * SAS], SAS);
            wmma::load_matrix_sync(al[i], &sAl[(wm + 16 * i) * SAS], SAS);
        }
#pragma unroll
        for (int j = 0; j < 2; j++) {
            wmma::load_matrix_sync(bh[j], &sBh[wn + 16 * j], SBS);
            wmma::load_matrix_sync(bl[j], &sBl[wn + 16 * j], SBS);
        }
#pragma unroll
        for (int i = 0; i < 2; i++)
#pragma unroll
            for (int j = 0; j < 2; j++) {
                wmma::mma_sync(acc[i][j], al[i], bh[j], acc[i][j]);
                wmma::mma_sync(acc[i][j], ah[i], bl[j], acc[i][j]);
                wmma::mma_sync(acc[i][j], ah[i], bh[j], acc[i][j]);
            }
        __syncthreads();
    }

    if (MODE == 0) {
        // direct store: no epilogue math, full tile, ldc multiple of 4
        bool direct = (bias == nullptr) && (addC == nullptr) && (act == 0) &&
                      ((ldc & 3) == 0) && (m0 + 128 <= M) && (n0 + 64 <= N);
        if (direct) {
#pragma unroll
            for (int i = 0; i < 2; i++)
#pragma unroll
                for (int j = 0; j < 2; j++)
                    wmma::store_matrix_sync(
                        &Cb[(long)(m0 + wm + 16 * i) * ldc + n0 + wn + 16 * j], acc[i][j], ldc,
                        wmma::mem_row_major);
            return;
        }
    }
#pragma unroll
    for (int i = 0; i < 2; i++)
#pragma unroll
        for (int j = 0; j < 2; j++)
            wmma::store_matrix_sync(&sC[(wm + 16 * i) * 72 + wn + 16 * j], acc[i][j], 72,
                                    wmma::mem_row_major);
    __syncthreads();

    if (MODE == 1) {
        // combine towers + degree scalers -> Z planes; tower = blockIdx.z
        int t = blockIdx.z;
        for (int i = tid; i < 128 * 15; i += 256) {
            int r = i / 15, f = i % 15;
            int gm = m0 + r;
            if (gm < M) {
                const float* row = &sC[r * 72];
                float v = row[f] + amp[gm] * row[15 + f] + invamp[gm] * row[30 + f] +
                          bias[t * 15 + f];
                long o = (long)gm * 80 + t * 15 + f;
                bsplit(v, &Zph[o], &Zpl[o]);
            }
        }
        return;
    }
    if (MODE == 2) {
        // Y = acc + bias + addC; accumulate BN column stats
        float s = 0.f, q = 0.f;
        int c = tid & 63, gn = n0 + c;
        for (int i = tid; i < 128 * 64; i += 256) {
            int r = i >> 6;
            int gm = m0 + r;
            if (gm < M && gn < N) {
                float v = sC[r * 72 + c] + bias[gn] + addC[(long)gm * ldadd + gn];
                Cb[(long)gm * ldc + gn] = v;
                s += v;
                q += v * v;
            }
        }
        rs[tid] = s;
        rq[tid] = q;
        __syncthreads();
        if (tid < 64 && gn < N) {
            float ts = rs[tid] + rs[tid + 64] + rs[tid + 128] + rs[tid + 192];
            float tq = rq[tid] + rq[tid + 64] + rq[tid + 128] + rq[tid + 192];
            atomicAdd(&bnS[gn], (double)ts);
            atomicAdd(&bnQ[gn], (double)tq);
        }
        return;
    }
    // MODE 0 generic
    for (int i = tid; i < 128 * 64; i += 256) {
        int r = i >> 6, c = i & 63;
        int gm = m0 + r, gn = n0 + c;
        if (gm < M && gn < N) {
            float v = sC[r * 72 + c];
            if (bias) v += bias[gn];
            if (addC) v += addC[(long)gm * ldadd + gn];
            if (act) v = fmaxf(v, 0.f);
            Cb[(long)gm * ldc + gn] = v;
        }
    }
}

// ---------------- tiny fp32 GEMM for the final MLP ----------------
__global__ void sgemm_s(const float* __restrict__ A, int lda, const float* __restrict__ B,
                        int ldb, float* __restrict__ C, int ldc, int M, int N, int K,
                        const float* __restrict__ bias, int act) {
    int i = blockIdx.x * blockDim.x + threadIdx.x;
    if (i >= M * N) return;
    int m = i / N, n = i % N;
    float s = bias ? bias[n] : 0.f;
    for (int k = 0; k < K; k++) s += A[m * lda + k] * B[k * ldb + n];
    if (act) s = fmaxf(s, 0.f);
    C[m * ldc + n] = s;
}

// ---------------- small utility kernels ----------------
__global__ void zero_i(int* p, int n) {
    int i = blockIdx.x * blockDim.x + threadIdx.x;
    if (i < n) p[i] = 0;
}
__global__ void zero_f(float* p, int n) {
    int i = blockIdx.x * blockDim.x + threadIdx.x;
    if (i < n) p[i] = 0.f;
}
__global__ void zero_bn(double* s, double* q, int n) {
    int i = blockIdx.x * blockDim.x + threadIdx.x;
    if (i < n) { s[i] = 0.0; q[i] = 0.0; }
}
__global__ void zero_zpad(bf16* Zh, bf16* Zl, bf16* Ah, bf16* Al) {
    int i = blockIdx.x * blockDim.x + threadIdx.x;
    if (i < NN * 5) {  // Z pad cols 75..79
        int n = i / 5, k = i % 5;
        Zh[n * 80 + 75 + k] = __float2bfloat16(0.f);
        Zl[n * 80 + 75 + k] = __float2bfloat16(0.f);
    }
    if (i < NN * 20) {  // AGG tower pad cols 300..303 (constant zero across layers)
        int n = i / 20, r = i % 20;
        int o = n * 1520 + (r >> 2) * 304 + 300 + (r & 3);
        Ah[o] = __float2bfloat16(0.f);
        Al[o] = __float2bfloat16(0.f);
    }
}

__global__ void hist_k(const int* __restrict__ ei, int* __restrict__ deg) {
    int e = blockIdx.x * blockDim.x + threadIdx.x;
    if (e < NE) atomicAdd(&deg[ei[NE + e]], 1);
}

__global__ void scan_chunks(const int* __restrict__ in, int* __restrict__ out,
                            int* __restrict__ bsum, int n) {
    __shared__ int s[512];
    int b = blockIdx.x, t = threadIdx.x;
    int idx = b * 512 + t;
    int v = (idx < n) ? in[idx] : 0;
    s[t] = v;
    __syncthreads();
    for (int off = 1; off < 512; off <<= 1) {
        int x = (t >= off) ? s[t - off] : 0;
        __syncthreads();
        s[t] += x;
        __syncthreads();
    }
    if (idx < n) out[idx] = s[t] - v;
    if (t == 511) bsum[b] = s[511];
}
__global__ void scan_sums(const int* __restrict__ sums, int* __restrict__ offs, int nb) {
    __shared__ int s[128];
    int t = threadIdx.x;
    int v = (t < nb) ? sums[t] : 0;
    s[t] = v;
    __syncthreads();
    for (int off = 1; off < 128; off <<= 1) {
        int x = (t >= off) ? s[t - off] : 0;
        __syncthreads();
        s[t] += x;
        __syncthreads();
    }
    if (t < nb) offs[t] = s[t] - v;
}
__global__ void scan_add(int* __restrict__ rowptr, const int* __restrict__ offs) {
    int i = blockIdx.x * blockDim.x + threadIdx.x;
    if (i < NN) rowptr[i] += offs[i >> 9];
    if (i == 0) rowptr[NN] = NE;
}

__global__ void fill_csr(const int* __restrict__ ei, const int* __restrict__ ea,
                         const int* __restrict__ rowptr, int* __restrict__ cursor,
                         int* __restrict__ csr) {
    int e = blockIdx.x * blockDim.x + threadIdx.x;
    if (e >= NE) return;
    int d = ei[NE + e];
    int pos = rowptr[d] + atomicAdd(&cursor[d], 1);
    csr[pos] = ei[e] | (ea[e] << 20);
}

__global__ void amp_k(const int* __restrict__ rowptr, float* __restrict__ amp,
                      float* __restrict__ invamp) {
    int i = blockIdx.x * blockDim.x + threadIdx.x;
    if (i >= NN) return;
    int dg = rowptr[i + 1] - rowptr[i];
    float a = logf((float)max(dg, 1) + 1.f) / AVGLOG;
    amp[i] = a;
    invamp[i] = 1.f / a;
}

// writes H hi/lo planes (ld 80, cols 75..79 zero)
__global__ void embed_k(const int* __restrict__ x, const float* __restrict__ emb,
                        bf16* __restrict__ Hh, bf16* __restrict__ Hl) {
    int i = blockIdx.x * blockDim.x + threadIdx.x;
    if (i >= NN * 80) return;
    int n = i / 80, f = i % 80;
    float v = (f < 75) ? emb[x[n] * 75 + f] : 0.f;
    bsplit(v, &Hh[i], &Hl[i]);
}

// ---------------- weight prep (bf16 planes) ----------------
__global__ void prep_wcat(const float* __restrict__ Wpre, bf16* __restrict__ Wh,
                          bf16* __restrict__ Wl) {
    int i = blockIdx.x * blockDim.x + threadIdx.x;
    if (i >= NL * 75 * 832) return;
    int l = i / (75 * 832), r = i % (75 * 832);
    int k = r / 832, j = r % 832;
    if (j >= 750 && j < 825) return;  // W0 region written by prep_w0
    float v = 0.f;
    if (j < 750) {
        int part = j / 375, j2 = j % 375;
        int t = j2 / 75, f = j2 % 75;
        int c = part * 75 + k;
        v = Wpre[((l * TW + t) * 225 + c) * 75 + f];
    }
    bsplit(v, &Wh[(l * 75 + k) * 832 + j], &Wl[(l * 75 + k) * 832 + j]);
}

__global__ void prep_w0(const float* __restrict__ Wpost, const float* __restrict__ Wlin,
                        bf16* __restrict__ Wh, bf16* __restrict__ Wl) {
    int i = blockIdx.x * blockDim.x + threadIdx.x;
    if (i >= NL * 75 * 75) return;
    int l = i / 5625, r = i % 5625;
    int k = r / 75, c = r % 75;
    float s = 0.f;
    for (int d = 0; d < 75; d++) {
        int t = d / 15, f = d % 15;
        s += Wpost[((l * TW + t) * 975 + k) * 15 + f] * Wlin[l * 5625 + d * 75 + c];
    }
    int o = (l * 75 + k) * 832 + 750 + c;
    bsplit(s, &Wh[o], &Wl[o]);
}

__global__ void prep_etab(const float* __restrict__ edge_emb, const float* __restrict__ We,
                          const float* __restrict__ be, const float* __restrict__ Wpre,
                          const float* __restrict__ bpre, float* __restrict__ Etab) {
    int a = blockIdx.x, l = blockIdx.y;
    __shared__ float ev[75];
    int t0 = threadIdx.x;
    if (t0 < 75) {
        float s = be[l * 75 + t0];
        for (int c = 0; c < 50; c++) s += edge_emb[a * 50 + c] * We[(l * 50 + c) * 75 + t0];
        ev[t0] = s;
    }
    __syncthreads();
    for (int j = t0; j < 375; j += blockDim.x) {
        int t = j / 75, f = j % 75;
        float s = bpre[(l * TW + t) * 75 + f];
        for (int d = 0; d < 75; d++)
            s += ev[d] * Wpre[((l * TW + t) * 225 + 150 + d) * 75 + f];
        Etab[(l * 4 + a) * 375 + j] = s;
    }
}

__global__ void prep_wg(const float* __restrict__ Wpost, bf16* __restrict__ Wh,
                        bf16* __restrict__ Wl) {
    int i = blockIdx.x * blockDim.x + threadIdx.x;
    if (i >= NL * TW * 300 * 48) return;
    int lt = i / (300 * 48), r = i % (300 * 48);
    int c = r / 48, col = r % 48;
    float v = 0.f;
    if (col < 45) {
        int g = col / 15, f = col % 15;
        v = Wpost[(lt * 975 + 75 + g * 300 + c) * 15 + f];
    }
    int o = (lt * 300 + c) * 48 + col;
    bsplit(v, &Wh[o], &Wl[o]);
}

__global__ void prep_wlin(const float* __restrict__ Wlin, bf16* __restrict__ Wh,
                          bf16* __restrict__ Wl) {
    int i = blockIdx.x * blockDim.x + threadIdx.x;
    if (i >= NL * 75 * 80) return;
    int l = i / (75 * 80), r = i % (75 * 80);
    int k = r / 80, c = r % 80;
    float v = (c < 75) ? Wlin[l * 5625 + k * 75 + c] : 0.f;
    int o = (l * 75 + k) * 80 + c;
    bsplit(v, &Wh[o], &Wl[o]);
}

// ---------------- PNA aggregation: writes AGG hi/lo planes [N][T][304] --------------
__global__ __launch_bounds__(384) void pna_agg(const float* __restrict__ CAB,
                                               const float* __restrict__ Etab,
                                               const int* __restrict__ rowptr,
                                               const int* __restrict__ csr,
                                               bf16* __restrict__ AGGh,
                                               bf16* __restrict__ AGGl) {
    int n = blockIdx.x;
    int j = threadIdx.x;
    if (j >= 375) return;
    float adst = CAB[(long)n * CLD + j];
    int beg = rowptr[n], end = rowptr[n + 1];
    float s = 0.f, sq = 0.f, mn = 3.4e38f, mx = -3.4e38f;
    int e = beg;
    for (; e + 1 < end; e += 2) {
        int p0 = csr[e], p1 = csr[e + 1];
        float b0 = CAB[(long)(p0 & 0xFFFFF) * CLD + 375 + j];
        float b1 = CAB[(long)(p1 & 0xFFFFF) * CLD + 375 + j];
        float v0 = adst + b0 + Etab[(p0 >> 20) * 375 + j];
        float v1 = adst + b1 + Etab[(p1 >> 20) * 375 + j];
        s += v0 + v1;
        sq += v0 * v0 + v1 * v1;
        mn = fminf(mn, fminf(v0, v1));
        mx = fmaxf(mx, fmaxf(v0, v1));
    }
    if (e < end) {
        int p0 = csr[e];
        float v0 = adst + CAB[(long)(p0 & 0xFFFFF) * CLD + 375 + j] + Etab[(p0 >> 20) * 375 + j];
        s += v0;
        sq += v0 * v0;
        mn = fminf(mn, v0);
        mx = fmaxf(mx, v0);
    }
    int dg = end - beg;
    float denom = fmaxf((float)dg, 1.f);
    float mean = s / denom, msq = sq / denom;
    float sd = sqrtf(fmaxf(msq - mean * mean, 0.f) + 1e-5f);
    if (dg == 0) { mn = 0.f; mx = 0.f; }
    int t = j / 75, f = j % 75;
    long o = (long)n * 1520 + t * 304;
    bsplit(mean, &AGGh[o + f], &AGGl[o + f]);
    bsplit(mn, &AGGh[o + 75 + f], &AGGl[o + 75 + f]);
    bsplit(mx, &AGGh[o + 150 + f], &AGGl[o + 150 + f]);
    bsplit(sd, &AGGh[o + 225 + f], &AGGl[o + 225 + f]);
}

// ---------------- BN apply + ReLU -> H hi/lo planes ----------------
__global__ void bn_apply(const float* __restrict__ Y, const double* __restrict__ S,
                         const double* __restrict__ Q, const float* __restrict__ gamma,
                         const float* __restrict__ beta, bf16* __restrict__ Hh,
                         bf16* __restrict__ Hl) {
    int i = blockIdx.x * blockDim.x + threadIdx.x;
    if (i >= NN * 80) return;
    int n = i / 80, f = i % 80;
    float v = 0.f;
    if (f < 75) {
        double mu = S[f] / (double)NN;
        double var = Q[f] / (double)NN - mu * mu;
        float inv = rsqrtf((float)var + 1e-5f);
        v = gamma[f] * ((Y[(long)n * DD + f] - (float)mu) * inv) + beta[f];
        v = fmaxf(v, 0.f);
    }
    bsplit(v, &Hh[i], &Hl[i]);
}

// ---------------- pooling (reconstruct fp32 from planes) ----------------
__global__ void pool_k(const int* __restrict__ batch, const bf16* __restrict__ Hh,
                       const bf16* __restrict__ Hl, float* __restrict__ pool) {
    int i = blockIdx.x * blockDim.x + threadIdx.x;
    if (i >= NN * DD) return;
    int n = i / DD, f = i % DD;
    float v = __bfloat162float(Hh[n * 80 + f]) + __bfloat162float(Hl[n * 80 + f]);
    atomicAdd(&pool[batch[n] * DD + f], v);
}

// ---------------- launch ----------------
template <int MODE>
static inline void tgemm(const bf16* Ah, const bf16* Al, int lda, long sA, const bf16* Bh,
                         const bf16* Bl, int ldb, long sB, float* C, int ldc, long sC, int M,
                         int N, int K, const float* bias, const float* addC, int ldadd,
                         const float* amp, const float* invamp, bf16* Zh, bf16* Zl,
                         double* bnS, double* bnQ, int act, int nz) {
    dim3 grid((N + 63) / 64, (M + 127) / 128, nz);
    tgemm_kernel<MODE><<<grid, 256, SMEM_BYTES>>>(Ah, Al, lda, sA, Bh, Bl, ldb, sB, C, ldc, sC,
                                                  M, N, K, bias, addC, ldadd, amp, invamp, Zh,
                                                  Zl, bnS, bnQ, act);
}

extern "C" void kernel_launch(void* const* d_in, const int* in_sizes, int n_in,
                              void* d_out, int out_size) {
    const int* x = (const int*)d_in[0];
    const int* ei = (const int*)d_in[1];
    const int* ea = (const int*)d_in[2];
    const int* batch = (const int*)d_in[3];
    const float* node_emb = (const float*)d_in[4];
    const float* edge_emb = (const float*)d_in[5];
    const float* We = (const float*)d_in[6];
    const float* be = (const float*)d_in[7];
    const float* Wpre = (const float*)d_in[8];
    const float* bpre = (const float*)d_in[9];
    const float* Wpost = (const float*)d_in[10];
    const float* bpost = (const float*)d_in[11];
    const float* Wlin = (const float*)d_in[12];
    const float* blin = (const float*)d_in[13];
    const float* gamma = (const float*)d_in[14];
    const float* beta = (const float*)d_in[15];
    const float* W1 = (const float*)d_in[16];
    const float* b1 = (const float*)d_in[17];
    const float* W2 = (const float*)d_in[18];
    const float* b2 = (const float*)d_in[19];
    const float* W3 = (const float*)d_in[20];
    const float* b3 = (const float*)d_in[21];
    float* out = (float*)d_out;

    cudaFuncSetAttribute(tgemm_kernel<0>, cudaFuncAttributeMaxDynamicSharedMemorySize,
                         SMEM_BYTES);
    cudaFuncSetAttribute(tgemm_kernel<1>, cudaFuncAttributeMaxDynamicSharedMemorySize,
                         SMEM_BYTES);
    cudaFuncSetAttribute(tgemm_kernel<2>, cudaFuncAttributeMaxDynamicSharedMemorySize,
                         SMEM_BYTES);

    bf16 *Hh, *Hl, *AGGh, *AGGl, *Zh, *Zl, *Wcath, *Wcatl, *WGh, *WGl, *Wlinh, *Wlinl;
    float *CAB, *Y, *amp, *invamp, *Etab, *pool, *z1, *z2;
    int *deg, *rowptr, *csr, *bsum, *boffs;
    double *bnS, *bnQ;
    cudaGetSymbolAddress((void**)&Hh, g_Hh);
    cudaGetSymbolAddress((void**)&Hl, g_Hl);
    cudaGetSymbolAddress((void**)&CAB, g_CAB);
    cudaGetSymbolAddress((void**)&AGGh, g_AGGh);
    cudaGetSymbolAddress((void**)&AGGl, g_AGGl);
    cudaGetSymbolAddress((void**)&Zh, g_Zh);
    cudaGetSymbolAddress((void**)&Zl, g_Zl);
    cudaGetSymbolAddress((void**)&Y, g_Y);
    cudaGetSymbolAddress((void**)&amp, g_amp);
    cudaGetSymbolAddress((void**)&invamp, g_invamp);
    cudaGetSymbolAddress((void**)&deg, g_deg);
    cudaGetSymbolAddress((void**)&rowptr, g_rowptr);
    cudaGetSymbolAddress((void**)&csr, g_csr);
    cudaGetSymbolAddress((void**)&bsum, g_bsum);
    cudaGetSymbolAddress((void**)&boffs, g_boffs);
    cudaGetSymbolAddress((void**)&Wcath, g_Wcath);
    cudaGetSymbolAddress((void**)&Wcatl, g_Wcatl);
    cudaGetSymbolAddress((void**)&Etab, g_Etab);
    cudaGetSymbolAddress((void**)&WGh, g_WGh);
    cudaGetSymbolAddress((void**)&WGl, g_WGl);
    cudaGetSymbolAddress((void**)&Wlinh, g_Wlinh);
    cudaGetSymbolAddress((void**)&Wlinl, g_Wlinl);
    cudaGetSymbolAddress((void**)&bnS, g_bnS);
    cudaGetSymbolAddress((void**)&bnQ, g_bnQ);
    cudaGetSymbolAddress((void**)&pool, g_pool);
    cudaGetSymbolAddress((void**)&z1, g_z1);
    cudaGetSymbolAddress((void**)&z2, g_z2);
    int* cursor = deg + NN;

    // ---- launch index 3 = layer-0 CAB GEMM (ncu capture slot) ----
    embed_k<<<(NN * 80 + 255) / 256, 256>>>(x, node_emb, Hh, Hl);               // 0
    prep_wcat<<<(NL * 75 * 832 + 255) / 256, 256>>>(Wpre, Wcath, Wcatl);        // 1
    prep_w0<<<(NL * 75 * 75 + 255) / 256, 256>>>(Wpost, Wlin, Wcath, Wcatl);    // 2
    tgemm<0>(Hh, Hl, 80, 0, Wcath, Wcatl, 832, 0, CAB, CLD, 0, NN, 825, 75,     // 3
             nullptr, nullptr, 0, nullptr, nullptr, nullptr, nullptr, nullptr, nullptr, 0, 1);
    prep_wg<<<(NL * TW * 300 * 48 + 255) / 256, 256>>>(Wpost, WGh, WGl);        // 4
    prep_wlin<<<(NL * 75 * 80 + 255) / 256, 256>>>(Wlin, Wlinh, Wlinl);         // 5
    zero_zpad<<<(NN * 20 + 255) / 256, 256>>>(Zh, Zl, AGGh, AGGl);              // 6
    zero_bn<<<(NL * DD + 255) / 256, 256>>>(bnS, bnQ, NL * DD);                 // 7

    // ---- graph structure prep ----
    zero_i<<<(2 * NN + 255) / 256, 256>>>(deg, 2 * NN);
    hist_k<<<(NE + 255) / 256, 256>>>(ei, deg);
    int nchunks = (NN + 511) / 512;
    scan_chunks<<<nchunks, 512>>>(deg, rowptr, bsum, NN);
    scan_sums<<<1, 128>>>(bsum, boffs, nchunks);
    scan_add<<<(NN + 255) / 256, 256>>>(rowptr, boffs);
    fill_csr<<<(NE + 255) / 256, 256>>>(ei, ea, rowptr, cursor, csr);
    amp_k<<<(NN + 255) / 256, 256>>>(rowptr, amp, invamp);
    prep_etab<<<dim3(4, NL), 384>>>(edge_emb, We, be, Wpre, bpre, Etab);

    // ---- layers ----
    for (int l = 0; l < NL; l++) {
        if (l > 0) {
            tgemm<0>(Hh, Hl, 80, 0, Wcath + l * 75 * 832, Wcatl + l * 75 * 832, 832, 0, CAB,
                     CLD, 0, NN, 825, 75, nullptr, nullptr, 0, nullptr, nullptr, nullptr,
                     nullptr, nullptr, nullptr, 0, 1);
        }
        pna_agg<<<NN, 384>>>(CAB, Etab + l * 4 * 375, rowptr, csr, AGGh, AGGl);
        // AGG GEMM + fused combine -> Z planes
        tgemm<1>(AGGh, AGGl, 1520, 304, WGh + l * TW * 300 * 48, WGl + l * TW * 300 * 48, 48,
                 (long)300 * 48, Y /*unused*/, 45, 0, NN, 45, 300, bpost + l * TW * FO, nullptr,
                 0, amp, invamp, Zh, Zl, nullptr, nullptr, 0, TW);
        // Y GEMM + fused BN stats
        tgemm<2>(Zh, Zl, 80, 0, Wlinh + l * 75 * 80, Wlinl + l * 75 * 80, 80, 0, Y, 75, 0, NN,
                 75, 75, blin + l * 75, CAB + 750, CLD, nullptr, nullptr, nullptr, nullptr,
                 bnS + l * DD, bnQ + l * DD, 0, 1);
        bn_apply<<<(NN * 80 + 255) / 256, 256>>>(Y, bnS + l * DD, bnQ + l * DD, gamma + l * DD,
                                                 beta + l * DD, Hh, Hl);
    }

    // ---- pooling + MLP (tiny, fp32 SIMT) ----
    zero_f<<<(NG * DD + 255) / 256, 256>>>(pool, NG * DD);
    pool_k<<<(NN * DD + 255) / 256, 256>>>(batch, Hh, Hl, pool);
    sgemm_s<<<(NG * 50 + 255) / 256, 256>>>(pool, 75, W1, 50, z1, 50, NG, 50, 75, b1, 1);
    sgemm_s<<<(NG * 25 + 255) / 256, 256>>>(z1, 50, W2, 25, z2, 25, NG, 25, 50, b2, 1);
    sgemm_s<<<(NG * 1 + 255) / 256, 256>>>(z2, 25, W3, 1, out, 1, NG, 1, 25, b3, 0);
}

// round 15
// speedup vs baseline: 1.1295x; 1.1295x over previous
#include <cuda_runtime.h>
#include <mma.h>
#include <math.h>
#include <cstdint>
#include <cuda_bf16.h>

using namespace nvcuda;

#define NN 50000
#define NE 150000
#define NG 2000
#define DD 75
#define TW 5
#define FO 15
#define NL 4
#define AVGLOG 1.1308269950720914f
#define CLD 828   // CAB row stride (multiple of 4 for wmma direct store)

typedef __nv_bfloat16 bf16;

// ---------------- scratch (device globals; no allocs) ----------------
__device__ __align__(256) bf16  g_Hh[NN * 80];
__device__ __align__(256) bf16  g_Hl[NN * 80];
__device__ __align__(256) float g_CAB[NN * CLD];     // fp32: [A(375) | B(375) | H@W0(75) | pad]
__device__ __align__(256) bf16  g_AGGh[NN * 1520];   // [N][T][304] padded towers
__device__ __align__(256) bf16  g_AGGl[NN * 1520];
__device__ __align__(256) bf16  g_Zh[NN * 80];
__device__ __align__(256) bf16  g_Zl[NN * 80];
__device__ float g_Y[NN * DD];
__device__ float g_amp[NN];
__device__ float g_invamp[NN];
__device__ int   g_deg[NN * 2];
__device__ int   g_rowptr[NN + 1];
__device__ int   g_csr[NE];
__device__ int   g_bsum[256];
__device__ int   g_boffs[256];
__device__ __align__(256) bf16  g_Wcath[NL * 75 * 832];
__device__ __align__(256) bf16  g_Wcatl[NL * 75 * 832];
__device__ float g_Etab[NL * 4 * 375];
__device__ __align__(256) bf16  g_WGh[NL * TW * 300 * 48];
__device__ __align__(256) bf16  g_WGl[NL * TW * 300 * 48];
__device__ __align__(256) bf16  g_Wlinh[NL * 75 * 80];
__device__ __align__(256) bf16  g_Wlinl[NL * 75 * 80];
__device__ double g_bnS[NL * DD];
__device__ double g_bnQ[NL * DD];
__device__ float g_pool[NG * DD];
__device__ float g_z1[NG * 50];
__device__ float g_z2[NG * 25];

__device__ __forceinline__ void bsplit(float v, bf16* h, bf16* l) {
    bf16 hi = __float2bfloat16(v);
    *h = hi;
    *l = __float2bfloat16(v - __bfloat162float(hi));
}

// ---------------- cp.async helpers ----------------
__device__ __forceinline__ void cp16(unsigned dst, const void* src, bool pred) {
    int sz = pred ? 16 : 0;   // sz=0 -> zero-fill
    asm volatile("cp.async.cg.shared.global [%0], [%1], 16, %2;\n" ::"r"(dst), "l"(src),
                 "r"(sz));
}
#define CP_COMMIT() asm volatile("cp.async.commit_group;\n" ::: "memory")
#define CP_WAIT1() asm volatile("cp.async.wait_group 1;\n" ::: "memory")
#define CP_WAIT0() asm volatile("cp.async.wait_group 0;\n" ::: "memory")

// ---------------- split-bf16 GEMM; pre-split hi/lo planes; 16B async loads ----------
// tile 128x64, 256 threads, 3 CTAs/SM (occ-4 spilled the mainloop: R14 regression).
// MODE 0: standard epilogue; MODE 1: PNA combine -> Z planes; MODE 2: Y + BN stats.
#define SAS 24
#define SBS 72
#define SA_PLANE (128 * SAS)
#define SB_PLANE (16 * SBS)
#define SMEM_BYTES (128 * 72 * 4)   // sC (36864) > stages (33792)

template <int MODE>
__global__ __launch_bounds__(256, 3) void tgemm_kernel(
    const bf16* __restrict__ Ah, const bf16* __restrict__ Al, int lda, long sAb,
    const bf16* __restrict__ Bh, const bf16* __restrict__ Bl, int ldb, long sBb,
    float* __restrict__ C, int ldc, long sCb,
    int M, int N, int K,
    const float* __restrict__ bias,
    const float* __restrict__ addC, int ldadd,
    const float* __restrict__ amp, const float* __restrict__ invamp,
    bf16* __restrict__ Zph, bf16* __restrict__ Zpl,
    double* __restrict__ bnS, double* __restrict__ bnQ,
    int act) {
    extern __shared__ char smem_raw[];
    __shared__ float rs[256], rq[256];
    bf16* bb = (bf16*)smem_raw;
    float* sC = (float*)smem_raw;

    const bf16* Abh = Ah + (long)blockIdx.z * sAb;
    const bf16* Abl = Al + (long)blockIdx.z * sAb;
    const bf16* Bbh = Bh + (long)blockIdx.z * sBb;
    const bf16* Bbl = Bl + (long)blockIdx.z * sBb;
    float* Cb = C + (long)blockIdx.z * sCb;
    int m0 = blockIdx.y * 128, n0 = blockIdx.x * 64;
    int tid = threadIdx.x;
    int warp = tid >> 5;
    int wm = (warp & 3) * 32;
    int wn = (warp >> 2) * 32;
    int numK = (K + 15) / 16;

    // ---- precomputed loader state ----
    const bf16* aSrc[2];
    unsigned aDst[2];
    bool aPred[2];
#pragma unroll
    for (int u = 0; u < 2; u++) {
        int idx = tid + u * 256;
        int pl = idx >> 8, rem = idx & 255;
        int r = rem >> 1, ch = rem & 1;
        const bf16* base = pl ? Abl : Abh;
        aPred[u] = (m0 + r) < M;
        aSrc[u] = base + (long)(m0 + r) * lda + ch * 8;
        aDst[u] = (unsigned)__cvta_generic_to_shared(bb + pl * 2 * SA_PLANE + r * SAS + ch * 8);
    }
    int bPl = tid >> 7, bRem = tid & 127;
    int bR = bRem >> 3, bCh = bRem & 7;
    const bf16* bBase = bPl ? Bbl : Bbh;
    bool bPredN = (n0 + bCh * 8) < ldb;
    const bf16* bSrc = bBase + (long)bR * ldb + n0 + bCh * 8;
    unsigned bDst = (unsigned)__cvta_generic_to_shared(bb + 4 * SA_PLANE + bPl * 2 * SB_PLANE +
                                                       bR * SBS + bCh * 8);

    auto load_stage = [&](int st, int k0) {
#pragma unroll
        for (int u = 0; u < 2; u++)
            cp16(aDst[u] + st * SA_PLANE * 2, aPred[u] ? (aSrc[u] + k0) : Abh, aPred[u]);
        bool p = bPredN && (k0 + bR) < K;
        cp16(bDst + st * SB_PLANE * 2, p ? (bSrc + (long)k0 * ldb) : Bbh, p);
    };

    wmma::fragment<wmma::accumulator, 16, 16, 16, float> acc[2][2];
#pragma unroll
    for (int i = 0; i < 2; i++)
#pragma unroll
        for (int j = 0; j < 2; j++) wmma::fill_fragment(acc[i][j], 0.f);

    load_stage(0, 0);
    CP_COMMIT();

    for (int kt = 0; kt < numK; kt++) {
        int st = kt & 1;
        if (kt + 1 < numK) {
            load_stage(st ^ 1, (kt + 1) * 16);
            CP_COMMIT();
            CP_WAIT1();
        } else {
            CP_WAIT0();
        }
        __syncthreads();

        bf16* sAh = bb + st * SA_PLANE;
        bf16* sAl = bb + 2 * SA_PLANE + st * SA_PLANE;
        bf16* sBh = bb + 4 * SA_PLANE + st * SB_PLANE;
        bf16* sBl = bb + 4 * SA_PLANE + 2 * SB_PLANE + st * SB_PLANE;

        wmma::fragment<wmma::matrix_a, 16, 16, 16, bf16, wmma::row_major> ah[2], al[2];
        wmma::fragment<wmma::matrix_b, 16, 16, 16, bf16, wmma::row_major> bh[2], bl[2];
#pragma unroll
        for (int i = 0; i < 2; i++) {
            wmma::load_matrix_sync(ah[i], &sAh[(wm + 16 * i) * SAS], SAS);
            wmma::load_matrix_sync(al[i], &sAl[(wm + 16 * i) * SAS], SAS);
        }
#pragma unroll
        for (int j = 0; j < 2; j++) {
            wmma::load_matrix_sync(bh[j], &sBh[wn + 16 * j], SBS);
            wmma::load_matrix_sync(bl[j], &sBl[wn + 16 * j], SBS);
        }
#pragma unroll
        for (int i = 0; i < 2; i++)
#pragma unroll
            for (int j = 0; j < 2; j++) {
                wmma::mma_sync(acc[i][j], al[i], bh[j], acc[i][j]);
                wmma::mma_sync(acc[i][j], ah[i], bl[j], acc[i][j]);
                wmma::mma_sync(acc[i][j], ah[i], bh[j], acc[i][j]);
            }
        __syncthreads();
    }

    if (MODE == 0) {
        // direct store: no epilogue math, full tile, ldc multiple of 4
        bool direct = (bias == nullptr) && (addC == nullptr) && (act == 0) &&
                      ((ldc & 3) == 0) && (m0 + 128 <= M) && (n0 + 64 <= N);
        if (direct) {
#pragma unroll
            for (int i = 0; i < 2; i++)
#pragma unroll
                for (int j = 0; j < 2; j++)
                    wmma::store_matrix_sync(
                        &Cb[(long)(m0 + wm + 16 * i) * ldc + n0 + wn + 16 * j], acc[i][j], ldc,
                        wmma::mem_row_major);
            return;
        }
    }
#pragma unroll
    for (int i = 0; i < 2; i++)
#pragma unroll
        for (int j = 0; j < 2; j++)
            wmma::store_matrix_sync(&sC[(wm + 16 * i) * 72 + wn + 16 * j], acc[i][j], 72,
                                    wmma::mem_row_major);
    __syncthreads();

    if (MODE == 1) {
        // combine towers + degree scalers -> Z planes; tower = blockIdx.z
        int t = blockIdx.z;
        for (int i = tid; i < 128 * 15; i += 256) {
            int r = i / 15, f = i % 15;
            int gm = m0 + r;
            if (gm < M) {
                const float* row = &sC[r * 72];
                float v = row[f] + amp[gm] * row[15 + f] + invamp[gm] * row[30 + f] +
                          bias[t * 15 + f];
                long o = (long)gm * 80 + t * 15 + f;
                bsplit(v, &Zph[o], &Zpl[o]);
            }
        }
        return;
    }
    if (MODE == 2) {
        // Y = acc + bias + addC; accumulate BN column stats
        float s = 0.f, q = 0.f;
        int c = tid & 63, gn = n0 + c;
        for (int i = tid; i < 128 * 64; i += 256) {
            int r = i >> 6;
            int gm = m0 + r;
            if (gm < M && gn < N) {
                float v = sC[r * 72 + c] + bias[gn] + addC[(long)gm * ldadd + gn];
                Cb[(long)gm * ldc + gn] = v;
                s += v;
                q += v * v;
            }
        }
        rs[tid] = s;
        rq[tid] = q;
        __syncthreads();
        if (tid < 64 && gn < N) {
            float ts = rs[tid] + rs[tid + 64] + rs[tid + 128] + rs[tid + 192];
            float tq = rq[tid] + rq[tid + 64] + rq[tid + 128] + rq[tid + 192];
            atomicAdd(&bnS[gn], (double)ts);
            atomicAdd(&bnQ[gn], (double)tq);
        }
        return;
    }
    // MODE 0 generic
    for (int i = tid; i < 128 * 64; i += 256) {
        int r = i >> 6, c = i & 63;
        int gm = m0 + r, gn = n0 + c;
        if (gm < M && gn < N) {
            float v = sC[r * 72 + c];
            if (bias) v += bias[gn];
            if (addC) v += addC[(long)gm * ldadd + gn];
            if (act) v = fmaxf(v, 0.f);
            Cb[(long)gm * ldc + gn] = v;
        }
    }
}

// ---------------- tiny fp32 GEMM for the final MLP ----------------
__global__ void sgemm_s(const float* __restrict__ A, int lda, const float* __restrict__ B,
                        int ldb, float* __restrict__ C, int ldc, int M, int N, int K,
                        const float* __restrict__ bias, int act) {
    int i = blockIdx.x * blockDim.x + threadIdx.x;
    if (i >= M * N) return;
    int m = i / N, n = i % N;
    float s = bias ? bias[n] : 0.f;
    for (int k = 0; k < K; k++) s += A[m * lda + k] * B[k * ldb + n];
    if (act) s = fmaxf(s, 0.f);
    C[m * ldc + n] = s;
}

// ---------------- small utility kernels ----------------
__global__ void zero_i(int* p, int n) {
    int i = blockIdx.x * blockDim.x + threadIdx.x;
    if (i < n) p[i] = 0;
}
__global__ void zero_f(float* p, int n) {
    int i = blockIdx.x * blockDim.x + threadIdx.x;
    if (i < n) p[i] = 0.f;
}
__global__ void zero_bn(double* s, double* q, int n) {
    int i = blockIdx.x * blockDim.x + threadIdx.x;
    if (i < n) { s[i] = 0.0; q[i] = 0.0; }
}
__global__ void zero_zpad(bf16* Zh, bf16* Zl, bf16* Ah, bf16* Al) {
    int i = blockIdx.x * blockDim.x + threadIdx.x;
    if (i < NN * 5) {  // Z pad cols 75..79
        int n = i / 5, k = i % 5;
        Zh[n * 80 + 75 + k] = __float2bfloat16(0.f);
        Zl[n * 80 + 75 + k] = __float2bfloat16(0.f);
    }
    if (i < NN * 20) {  // AGG tower pad cols 300..303 (constant zero across layers)
        int n = i / 20, r = i % 20;
        int o = n * 1520 + (r >> 2) * 304 + 300 + (r & 3);
        Ah[o] = __float2bfloat16(0.f);
        Al[o] = __float2bfloat16(0.f);
    }
}

__global__ void hist_k(const int* __restrict__ ei, int* __restrict__ deg) {
    int e = blockIdx.x * blockDim.x + threadIdx.x;
    if (e < NE) atomicAdd(&deg[ei[NE + e]], 1);
}

__global__ void scan_chunks(const int* __restrict__ in, int* __restrict__ out,
                            int* __restrict__ bsum, int n) {
    __shared__ int s[512];
    int b = blockIdx.x, t = threadIdx.x;
    int idx = b * 512 + t;
    int v = (idx < n) ? in[idx] : 0;
    s[t] = v;
    __syncthreads();
    for (int off = 1; off < 512; off <<= 1) {
        int x = (t >= off) ? s[t - off] : 0;
        __syncthreads();
        s[t] += x;
        __syncthreads();
    }
    if (idx < n) out[idx] = s[t] - v;
    if (t == 511) bsum[b] = s[511];
}
__global__ void scan_sums(const int* __restrict__ sums, int* __restrict__ offs, int nb) {
    __shared__ int s[128];
    int t = threadIdx.x;
    int v = (t < nb) ? sums[t] : 0;
    s[t] = v;
    __syncthreads();
    for (int off = 1; off < 128; off <<= 1) {
        int x = (t >= off) ? s[t - off] : 0;
        __syncthreads();
        s[t] += x;
        __syncthreads();
    }
    if (t < nb) offs[t] = s[t] - v;
}
__global__ void scan_add(int* __restrict__ rowptr, const int* __restrict__ offs) {
    int i = blockIdx.x * blockDim.x + threadIdx.x;
    if (i < NN) rowptr[i] += offs[i >> 9];
    if (i == 0) rowptr[NN] = NE;
}

__global__ void fill_csr(const int* __restrict__ ei, const int* __restrict__ ea,
                         const int* __restrict__ rowptr, int* __restrict__ cursor,
                         int* __restrict__ csr) {
    int e = blockIdx.x * blockDim.x + threadIdx.x;
    if (e >= NE) return;
    int d = ei[NE + e];
    int pos = rowptr[d] + atomicAdd(&cursor[d], 1);
    csr[pos] = ei[e] | (ea[e] << 20);
}

__global__ void amp_k(const int* __restrict__ rowptr, float* __restrict__ amp,
                      float* __restrict__ invamp) {
    int i = blockIdx.x * blockDim.x + threadIdx.x;
    if (i >= NN) return;
    int dg = rowptr[i + 1] - rowptr[i];
    float a = logf((float)max(dg, 1) + 1.f) / AVGLOG;
    amp[i] = a;
    invamp[i] = 1.f / a;
}

// writes H hi/lo planes (ld 80, cols 75..79 zero)
__global__ void embed_k(const int* __restrict__ x, const float* __restrict__ emb,
                        bf16* __restrict__ Hh, bf16* __restrict__ Hl) {
    int i = blockIdx.x * blockDim.x + threadIdx.x;
    if (i >= NN * 80) return;
    int n = i / 80, f = i % 80;
    float v = (f < 75) ? emb[x[n] * 75 + f] : 0.f;
    bsplit(v, &Hh[i], &Hl[i]);
}

// ---------------- weight prep (bf16 planes) ----------------
__global__ void prep_wcat(const float* __restrict__ Wpre, bf16* __restrict__ Wh,
                          bf16* __restrict__ Wl) {
    int i = blockIdx.x * blockDim.x + threadIdx.x;
    if (i >= NL * 75 * 832) return;
    int l = i / (75 * 832), r = i % (75 * 832);
    int k = r / 832, j = r % 832;
    if (j >= 750 && j < 825) return;  // W0 region written by prep_w0
    float v = 0.f;
    if (j < 750) {
        int part = j / 375, j2 = j % 375;
        int t = j2 / 75, f = j2 % 75;
        int c = part * 75 + k;
        v = Wpre[((l * TW + t) * 225 + c) * 75 + f];
    }
    bsplit(v, &Wh[(l * 75 + k) * 832 + j], &Wl[(l * 75 + k) * 832 + j]);
}

__global__ void prep_w0(const float* __restrict__ Wpost, const float* __restrict__ Wlin,
                        bf16* __restrict__ Wh, bf16* __restrict__ Wl) {
    int i = blockIdx.x * blockDim.x + threadIdx.x;
    if (i >= NL * 75 * 75) return;
    int l = i / 5625, r = i % 5625;
    int k = r / 75, c = r % 75;
    float s = 0.f;
    for (int d = 0; d < 75; d++) {
        int t = d / 15, f = d % 15;
        s += Wpost[((l * TW + t) * 975 + k) * 15 + f] * Wlin[l * 5625 + d * 75 + c];
    }
    int o = (l * 75 + k) * 832 + 750 + c;
    bsplit(s, &Wh[o], &Wl[o]);
}

__global__ void prep_etab(const float* __restrict__ edge_emb, const float* __restrict__ We,
                          const float* __restrict__ be, const float* __restrict__ Wpre,
                          const float* __restrict__ bpre, float* __restrict__ Etab) {
    int a = blockIdx.x, l = blockIdx.y;
    __shared__ float ev[75];
    int t0 = threadIdx.x;
    if (t0 < 75) {
        float s = be[l * 75 + t0];
        for (int c = 0; c < 50; c++) s += edge_emb[a * 50 + c] * We[(l * 50 + c) * 75 + t0];
        ev[t0] = s;
    }
    __syncthreads();
    for (int j = t0; j < 375; j += blockDim.x) {
        int t = j / 75, f = j % 75;
        float s = bpre[(l * TW + t) * 75 + f];
        for (int d = 0; d < 75; d++)
            s += ev[d] * Wpre[((l * TW + t) * 225 + 150 + d) * 75 + f];
        Etab[(l * 4 + a) * 375 + j] = s;
    }
}

__global__ void prep_wg(const float* __restrict__ Wpost, bf16* __restrict__ Wh,
                        bf16* __restrict__ Wl) {
    int i = blockIdx.x * blockDim.x + threadIdx.x;
    if (i >= NL * TW * 300 * 48) return;
    int lt = i / (300 * 48), r = i % (300 * 48);
    int c = r / 48, col = r % 48;
    float v = 0.f;
    if (col < 45) {
        int g = col / 15, f = col % 15;
        v = Wpost[(lt * 975 + 75 + g * 300 + c) * 15 + f];
    }
    int o = (lt * 300 + c) * 48 + col;
    bsplit(v, &Wh[o], &Wl[o]);
}

__global__ void prep_wlin(const float* __restrict__ Wlin, bf16* __restrict__ Wh,
                          bf16* __restrict__ Wl) {
    int i = blockIdx.x * blockDim.x + threadIdx.x;
    if (i >= NL * 75 * 80) return;
    int l = i / (75 * 80), r = i % (75 * 80);
    int k = r / 80, c = r % 80;
    float v = (c < 75) ? Wlin[l * 5625 + k * 75 + c] : 0.f;
    int o = (l * 75 + k) * 80 + c;
    bsplit(v, &Wh[o], &Wl[o]);
}

// ---------------- PNA aggregation: writes AGG hi/lo planes [N][T][304] --------------
__global__ __launch_bounds__(384) void pna_agg(const float* __restrict__ CAB,
                                               const float* __restrict__ Etab,
                                               const int* __restrict__ rowptr,
                                               const int* __restrict__ csr,
                                               bf16* __restrict__ AGGh,
                                               bf16* __restrict__ AGGl) {
    int n = blockIdx.x;
    int j = threadIdx.x;
    if (j >= 375) return;
    float adst = CAB[(long)n * CLD + j];
    int beg = rowptr[n], end = rowptr[n + 1];
    float s = 0.f, sq = 0.f, mn = 3.4e38f, mx = -3.4e38f;
    int e = beg;
    for (; e + 1 < end; e += 2) {
        int p0 = csr[e], p1 = csr[e + 1];
        float b0 = CAB[(long)(p0 & 0xFFFFF) * CLD + 375 + j];
        float b1 = CAB[(long)(p1 & 0xFFFFF) * CLD + 375 + j];
        float v0 = adst + b0 + Etab[(p0 >> 20) * 375 + j];
        float v1 = adst + b1 + Etab[(p1 >> 20) * 375 + j];
        s += v0 + v1;
        sq += v0 * v0 + v1 * v1;
        mn = fminf(mn, fminf(v0, v1));
        mx = fmaxf(mx, fmaxf(v0, v1));
    }
    if (e < end) {
        int p0 = csr[e];
        float v0 = adst + CAB[(long)(p0 & 0xFFFFF) * CLD + 375 + j] + Etab[(p0 >> 20) * 375 + j];
        s += v0;
        sq += v0 * v0;
        mn = fminf(mn, v0);
        mx = fmaxf(mx, v0);
    }
    int dg = end - beg;
    float denom = fmaxf((float)dg, 1.f);
    float mean = s / denom, msq = sq / denom;
    float sd = sqrtf(fmaxf(msq - mean * mean, 0.f) + 1e-5f);
    if (dg == 0) { mn = 0.f; mx = 0.f; }
    int t = j / 75, f = j % 75;
    long o = (long)n * 1520 + t * 304;
    bsplit(mean, &AGGh[o + f], &AGGl[o + f]);
    bsplit(mn, &AGGh[o + 75 + f], &AGGl[o + 75 + f]);
    bsplit(mx, &AGGh[o + 150 + f], &AGGl[o + 150 + f]);
    bsplit(sd, &AGGh[o + 225 + f], &AGGl[o + 225 + f]);
}

// ---------------- BN apply + ReLU -> H hi/lo planes ----------------
__global__ void bn_apply(const float* __restrict__ Y, const double* __restrict__ S,
                         const double* __restrict__ Q, const float* __restrict__ gamma,
                         const float* __restrict__ beta, bf16* __restrict__ Hh,
                         bf16* __restrict__ Hl) {
    int i = blockIdx.x * blockDim.x + threadIdx.x;
    if (i >= NN * 80) return;
    int n = i / 80, f = i % 80;
    float v = 0.f;
    if (f < 75) {
        double mu = S[f] / (double)NN;
        double var = Q[f] / (double)NN - mu * mu;
        float inv = rsqrtf((float)var + 1e-5f);
        v = gamma[f] * ((Y[(long)n * DD + f] - (float)mu) * inv) + beta[f];
        v = fmaxf(v, 0.f);
    }
    bsplit(v, &Hh[i], &Hl[i]);
}

// ---------------- pooling (reconstruct fp32 from planes) ----------------
__global__ void pool_k(const int* __restrict__ batch, const bf16* __restrict__ Hh,
                       const bf16* __restrict__ Hl, float* __restrict__ pool) {
    int i = blockIdx.x * blockDim.x + threadIdx.x;
    if (i >= NN * DD) return;
    int n = i / DD, f = i % DD;
    float v = __bfloat162float(Hh[n * 80 + f]) + __bfloat162float(Hl[n * 80 + f]);
    atomicAdd(&pool[batch[n] * DD + f], v);
}

// ---------------- launch ----------------
template <int MODE>
static inline void tgemm(const bf16* Ah, const bf16* Al, int lda, long sA, const bf16* Bh,
                         const bf16* Bl, int ldb, long sB, float* C, int ldc, long sC, int M,
                         int N, int K, const float* bias, const float* addC, int ldadd,
                         const float* amp, const float* invamp, bf16* Zh, bf16* Zl,
                         double* bnS, double* bnQ, int act, int nz) {
    dim3 grid((N + 63) / 64, (M + 127) / 128, nz);
    tgemm_kernel<MODE><<<grid, 256, SMEM_BYTES>>>(Ah, Al, lda, sA, Bh, Bl, ldb, sB, C, ldc, sC,
                                                  M, N, K, bias, addC, ldadd, amp, invamp, Zh,
                                                  Zl, bnS, bnQ, act);
}

extern "C" void kernel_launch(void* const* d_in, const int* in_sizes, int n_in,
                              void* d_out, int out_size) {
    const int* x = (const int*)d_in[0];
    const int* ei = (const int*)d_in[1];
    const int* ea = (const int*)d_in[2];
    const int* batch = (const int*)d_in[3];
    const float* node_emb = (const float*)d_in[4];
    const float* edge_emb = (const float*)d_in[5];
    const float* We = (const float*)d_in[6];
    const float* be = (const float*)d_in[7];
    const float* Wpre = (const float*)d_in[8];
    const float* bpre = (const float*)d_in[9];
    const float* Wpost = (const float*)d_in[10];
    const float* bpost = (const float*)d_in[11];
    const float* Wlin = (const float*)d_in[12];
    const float* blin = (const float*)d_in[13];
    const float* gamma = (const float*)d_in[14];
    const float* beta = (const float*)d_in[15];
    const float* W1 = (const float*)d_in[16];
    const float* b1 = (const float*)d_in[17];
    const float* W2 = (const float*)d_in[18];
    const float* b2 = (const float*)d_in[19];
    const float* W3 = (const float*)d_in[20];
    const float* b3 = (const float*)d_in[21];
    float* out = (float*)d_out;

    cudaFuncSetAttribute(tgemm_kernel<0>, cudaFuncAttributeMaxDynamicSharedMemorySize,
                         SMEM_BYTES);
    cudaFuncSetAttribute(tgemm_kernel<1>, cudaFuncAttributeMaxDynamicSharedMemorySize,
                         SMEM_BYTES);
    cudaFuncSetAttribute(tgemm_kernel<2>, cudaFuncAttributeMaxDynamicSharedMemorySize,
                         SMEM_BYTES);

    bf16 *Hh, *Hl, *AGGh, *AGGl, *Zh, *Zl, *Wcath, *Wcatl, *WGh, *WGl, *Wlinh, *Wlinl;
    float *CAB, *Y, *amp, *invamp, *Etab, *pool, *z1, *z2;
    int *deg, *rowptr, *csr, *bsum, *boffs;
    double *bnS, *bnQ;
    cudaGetSymbolAddress((void**)&Hh, g_Hh);
    cudaGetSymbolAddress((void**)&Hl, g_Hl);
    cudaGetSymbolAddress((void**)&CAB, g_CAB);
    cudaGetSymbolAddress((void**)&AGGh, g_AGGh);
    cudaGetSymbolAddress((void**)&AGGl, g_AGGl);
    cudaGetSymbolAddress((void**)&Zh, g_Zh);
    cudaGetSymbolAddress((void**)&Zl, g_Zl);
    cudaGetSymbolAddress((void**)&Y, g_Y);
    cudaGetSymbolAddress((void**)&amp, g_amp);
    cudaGetSymbolAddress((void**)&invamp, g_invamp);
    cudaGetSymbolAddress((void**)&deg, g_deg);
    cudaGetSymbolAddress((void**)&rowptr, g_rowptr);
    cudaGetSymbolAddress((void**)&csr, g_csr);
    cudaGetSymbolAddress((void**)&bsum, g_bsum);
    cudaGetSymbolAddress((void**)&boffs, g_boffs);
    cudaGetSymbolAddress((void**)&Wcath, g_Wcath);
    cudaGetSymbolAddress((void**)&Wcatl, g_Wcatl);
    cudaGetSymbolAddress((void**)&Etab, g_Etab);
    cudaGetSymbolAddress((void**)&WGh, g_WGh);
    cudaGetSymbolAddress((void**)&WGl, g_WGl);
    cudaGetSymbolAddress((void**)&Wlinh, g_Wlinh);
    cudaGetSymbolAddress((void**)&Wlinl, g_Wlinl);
    cudaGetSymbolAddress((void**)&bnS, g_bnS);
    cudaGetSymbolAddress((void**)&bnQ, g_bnQ);
    cudaGetSymbolAddress((void**)&pool, g_pool);
    cudaGetSymbolAddress((void**)&z1, g_z1);
    cudaGetSymbolAddress((void**)&z2, g_z2);
    int* cursor = deg + NN;

    // ---- launch index 3 = layer-0 CAB GEMM (ncu capture slot) ----
    embed_k<<<(NN * 80 + 255) / 256, 256>>>(x, node_emb, Hh, Hl);               // 0
    prep_wcat<<<(NL * 75 * 832 + 255) / 256, 256>>>(Wpre, Wcath, Wcatl);        // 1
    prep_w0<<<(NL * 75 * 75 + 255) / 256, 256>>>(Wpost, Wlin, Wcath, Wcatl);    // 2
    tgemm<0>(Hh, Hl, 80, 0, Wcath, Wcatl, 832, 0, CAB, CLD, 0, NN, 825, 75,     // 3
             nullptr, nullptr, 0, nullptr, nullptr, nullptr, nullptr, nullptr, nullptr, 0, 1);
    prep_wg<<<(NL * TW * 300 * 48 + 255) / 256, 256>>>(Wpost, WGh, WGl);        // 4
    prep_wlin<<<(NL * 75 * 80 + 255) / 256, 256>>>(Wlin, Wlinh, Wlinl);         // 5
    zero_zpad<<<(NN * 20 + 255) / 256, 256>>>(Zh, Zl, AGGh, AGGl);              // 6
    zero_bn<<<(NL * DD + 255) / 256, 256>>>(bnS, bnQ, NL * DD);                 // 7

    // ---- graph structure prep ----
    zero_i<<<(2 * NN + 255) / 256, 256>>>(deg, 2 * NN);
    hist_k<<<(NE + 255) / 256, 256>>>(ei, deg);
    int nchunks = (NN + 511) / 512;
    scan_chunks<<<nchunks, 512>>>(deg, rowptr, bsum, NN);
    scan_sums<<<1, 128>>>(bsum, boffs, nchunks);
    scan_add<<<(NN + 255) / 256, 256>>>(rowptr, boffs);
    fill_csr<<<(NE + 255) / 256, 256>>>(ei, ea, rowptr, cursor, csr);
    amp_k<<<(NN + 255) / 256, 256>>>(rowptr, amp, invamp);
    prep_etab<<<dim3(4, NL), 384>>>(edge_emb, We, be, Wpre, bpre, Etab);

    // ---- layers ----
    for (int l = 0; l < NL; l++) {
        if (l > 0) {
            tgemm<0>(Hh, Hl, 80, 0, Wcath + l * 75 * 832, Wcatl + l * 75 * 832, 832, 0, CAB,
                     CLD, 0, NN, 825, 75, nullptr, nullptr, 0, nullptr, nullptr, nullptr,
                     nullptr, nullptr, nullptr, 0, 1);
        }
        pna_agg<<<NN, 384>>>(CAB, Etab + l * 4 * 375, rowptr, csr, AGGh, AGGl);
        // AGG GEMM + fused combine -> Z planes
        tgemm<1>(AGGh, AGGl, 1520, 304, WGh + l * TW * 300 * 48, WGl + l * TW * 300 * 48, 48,
                 (long)300 * 48, Y /*unused*/, 45, 0, NN, 45, 300, bpost + l * TW * FO, nullptr,
                 0, amp, invamp, Zh, Zl, nullptr, nullptr, 0, TW);
        // Y GEMM + fused BN stats
        tgemm<2>(Zh, Zl, 80, 0, Wlinh + l * 75 * 80, Wlinl + l * 75 * 80, 80, 0, Y, 75, 0, NN,
                 75, 75, blin + l * 75, CAB + 750, CLD, nullptr, nullptr, nullptr, nullptr,
                 bnS + l * DD, bnQ + l * DD, 0, 1);
        bn_apply<<<(NN * 80 + 255) / 256, 256>>>(Y, bnS + l * DD, bnQ + l * DD, gamma + l * DD,
                                                 beta + l * DD, Hh, Hl);
    }

    // ---- pooling + MLP (tiny, fp32 SIMT) ----
    zero_f<<<(NG * DD + 255) / 256, 256>>>(pool, NG * DD);
    pool_k<<<(NN * DD + 255) / 256, 256>>>(batch, Hh, Hl, pool);
    sgemm_s<<<(NG * 50 + 255) / 256, 256>>>(pool, 75, W1, 50, z1, 50, NG, 50, 75, b1, 1);
    sgemm_s<<<(NG * 25 + 255) / 256, 256>>>(z1, 50, W2, 25, z2, 25, NG, 25, 50, b2, 1);
    sgemm_s<<<(NG * 1 + 255) / 256, 256>>>(z2, 25, W3, 1, out, 1, NG, 1, 25, b3, 0);
}

// round 17
// speedup vs baseline: 1.1624x; 1.0291x over previous
#include <cuda_runtime.h>
#include <mma.h>
#include <math.h>
#include <cstdint>
#include <cuda_bf16.h>

using namespace nvcuda;

#define NN 50000
#define NE 150000
#define NG 2000
#define DD 75
#define TW 5
#define FO 15
#define NL 4
#define AVGLOG 1.1308269950720914f
#define CLD 828   // CAB row stride (multiple of 4 for wmma direct store)

typedef __nv_bfloat16 bf16;

// ---------------- scratch (device globals; no allocs) ----------------
__device__ __align__(256) bf16  g_Hh[NN * 80];
__device__ __align__(256) bf16  g_Hl[NN * 80];
__device__ __align__(256) float g_CAB[NN * CLD];     // fp32: [A(375) | B(375) | H@W0(75) | pad]
__device__ __align__(256) bf16  g_AGGh[NN * 1520];   // [N][T][304] padded towers
__device__ __align__(256) bf16  g_AGGl[NN * 1520];
__device__ __align__(256) bf16  g_Zh[NN * 80];
__device__ __align__(256) bf16  g_Zl[NN * 80];
__device__ float g_Y[NN * DD];
__device__ float g_amp[NN];
__device__ float g_invamp[NN];
__device__ int   g_deg[NN * 2];
__device__ int   g_rowptr[NN + 1];
__device__ int   g_csr[NE];
__device__ int   g_bsum[256];
__device__ int   g_boffs[256];
__device__ __align__(256) bf16  g_Wcath[NL * 75 * 832];
__device__ __align__(256) bf16  g_Wcatl[NL * 75 * 832];
__device__ float g_Etab[NL * 4 * 375];
__device__ __align__(256) bf16  g_WGh[NL * TW * 300 * 48];
__device__ __align__(256) bf16  g_WGl[NL * TW * 300 * 48];
__device__ __align__(256) bf16  g_Wlinh[NL * 75 * 80];
__device__ __align__(256) bf16  g_Wlinl[NL * 75 * 80];
__device__ double g_bnS[NL * DD];
__device__ double g_bnQ[NL * DD];
__device__ float g_pool[NG * DD];
__device__ float g_z1[NG * 50];
__device__ float g_z2[NG * 25];

__device__ __forceinline__ void bsplit(float v, bf16* h, bf16* l) {
    bf16 hi = __float2bfloat16(v);
    *h = hi;
    *l = __float2bfloat16(v - __bfloat162float(hi));
}

// ---------------- cp.async helpers ----------------
__device__ __forceinline__ void cp16(unsigned dst, const void* src, bool pred) {
    int sz = pred ? 16 : 0;   // NOTE: sz=0 still ZERO-FILLS dst (16B write)
    asm volatile("cp.async.cg.shared.global [%0], [%1], 16, %2;\n" ::"r"(dst), "l"(src),
                 "r"(sz));
}
#define CP_COMMIT() asm volatile("cp.async.commit_group;\n" ::: "memory")
#define CP_WAIT1() asm volatile("cp.async.wait_group 1;\n" ::: "memory")
#define CP_WAIT0() asm volatile("cp.async.wait_group 0;\n" ::: "memory")

// ---------------- split-bf16 GEMM 128x64 (MODE 0/2); pre-split planes ----------------
#define SAS 24
#define SBS 72
#define SA_PLANE (128 * SAS)
#define SB_PLANE (16 * SBS)
#define SMEM_BYTES (128 * 72 * 4)

template <int MODE>
__global__ __launch_bounds__(256, 3) void tgemm_kernel(
    const bf16* __restrict__ Ah, const bf16* __restrict__ Al, int lda, long sAb,
    const bf16* __restrict__ Bh, const bf16* __restrict__ Bl, int ldb, long sBb,
    float* __restrict__ C, int ldc, long sCb,
    int M, int N, int K,
    const float* __restrict__ bias,
    const float* __restrict__ addC, int ldadd,
    double* __restrict__ bnS, double* __restrict__ bnQ,
    int act) {
    extern __shared__ char smem_raw[];
    __shared__ float rs[256], rq[256];
    bf16* bb = (bf16*)smem_raw;
    float* sC = (float*)smem_raw;

    const bf16* Abh = Ah + (long)blockIdx.z * sAb;
    const bf16* Abl = Al + (long)blockIdx.z * sAb;
    const bf16* Bbh = Bh + (long)blockIdx.z * sBb;
    const bf16* Bbl = Bl + (long)blockIdx.z * sBb;
    float* Cb = C + (long)blockIdx.z * sCb;
    int m0 = blockIdx.y * 128, n0 = blockIdx.x * 64;
    int tid = threadIdx.x;
    int warp = tid >> 5;
    int wm = (warp & 3) * 32;
    int wn = (warp >> 2) * 32;
    int numK = (K + 15) / 16;

    const bf16* aSrc[2];
    unsigned aDst[2];
    bool aPred[2];
#pragma unroll
    for (int u = 0; u < 2; u++) {
        int idx = tid + u * 256;
        int pl = idx >> 8, rem = idx & 255;
        int r = rem >> 1, ch = rem & 1;
        const bf16* base = pl ? Abl : Abh;
        aPred[u] = (m0 + r) < M;
        aSrc[u] = base + (long)(m0 + r) * lda + ch * 8;
        aDst[u] = (unsigned)__cvta_generic_to_shared(bb + pl * 2 * SA_PLANE + r * SAS + ch * 8);
    }
    int bPl = tid >> 7, bRem = tid & 127;
    int bR = bRem >> 3, bCh = bRem & 7;
    const bf16* bBase = bPl ? Bbl : Bbh;
    bool bPredN = (n0 + bCh * 8) < ldb;
    const bf16* bSrc = bBase + (long)bR * ldb + n0 + bCh * 8;
    unsigned bDst = (unsigned)__cvta_generic_to_shared(bb + 4 * SA_PLANE + bPl * 2 * SB_PLANE +
                                                       bR * SBS + bCh * 8);

    auto load_stage = [&](int st, int k0) {
#pragma unroll
        for (int u = 0; u < 2; u++)
            cp16(aDst[u] + st * SA_PLANE * 2, aPred[u] ? (aSrc[u] + k0) : Abh, aPred[u]);
        bool p = bPredN && (k0 + bR) < K;
        cp16(bDst + st * SB_PLANE * 2, p ? (bSrc + (long)k0 * ldb) : Bbh, p);
    };

    wmma::fragment<wmma::accumulator, 16, 16, 16, float> acc[2][2];
#pragma unroll
    for (int i = 0; i < 2; i++)
#pragma unroll
        for (int j = 0; j < 2; j++) wmma::fill_fragment(acc[i][j], 0.f);

    load_stage(0, 0);
    CP_COMMIT();

    for (int kt = 0; kt < numK; kt++) {
        int st = kt & 1;
        if (kt + 1 < numK) {
            load_stage(st ^ 1, (kt + 1) * 16);
            CP_COMMIT();
            CP_WAIT1();
        } else {
            CP_WAIT0();
        }
        __syncthreads();

        bf16* sAh = bb + st * SA_PLANE;
        bf16* sAl = bb + 2 * SA_PLANE + st * SA_PLANE;
        bf16* sBh = bb + 4 * SA_PLANE + st * SB_PLANE;
        bf16* sBl = bb + 4 * SA_PLANE + 2 * SB_PLANE + st * SB_PLANE;

        wmma::fragment<wmma::matrix_a, 16, 16, 16, bf16, wmma::row_major> ah[2], al[2];
        wmma::fragment<wmma::matrix_b, 16, 16, 16, bf16, wmma::row_major> bh[2], bl[2];
#pragma unroll
        for (int i = 0; i < 2; i++) {
            wmma::load_matrix_sync(ah[i], &sAh[(wm + 16 * i) * SAS], SAS);
            wmma::load_matrix_sync(al[i], &sAl[(wm + 16 * i) * SAS], SAS);
        }
#pragma unroll
        for (int j = 0; j < 2; j++) {
            wmma::load_matrix_sync(bh[j], &sBh[wn + 16 * j], SBS);
            wmma::load_matrix_sync(bl[j], &sBl[wn + 16 * j], SBS);
        }
#pragma unroll
        for (int i = 0; i < 2; i++)
#pragma unroll
            for (int j = 0; j < 2; j++) {
                wmma::mma_sync(acc[i][j], al[i], bh[j], acc[i][j]);
                wmma::mma_sync(acc[i][j], ah[i], bl[j], acc[i][j]);
                wmma::mma_sync(acc[i][j], ah[i], bh[j], acc[i][j]);
            }
        __syncthreads();
    }

    if (MODE == 0) {
        bool direct = (bias == nullptr) && (addC == nullptr) && (act == 0) &&
                      ((ldc & 3) == 0) && (m0 + 128 <= M) && (n0 + 64 <= N);
        if (direct) {
#pragma unroll
            for (int i = 0; i < 2; i++)
#pragma unroll
                for (int j = 0; j < 2; j++)
                    wmma::store_matrix_sync(
                        &Cb[(long)(m0 + wm + 16 * i) * ldc + n0 + wn + 16 * j], acc[i][j], ldc,
                        wmma::mem_row_major);
            return;
        }
    }
#pragma unroll
    for (int i = 0; i < 2; i++)
#pragma unroll
        for (int j = 0; j < 2; j++)
            wmma::store_matrix_sync(&sC[(wm + 16 * i) * 72 + wn + 16 * j], acc[i][j], 72,
                                    wmma::mem_row_major);
    __syncthreads();

    if (MODE == 2) {
        float s = 0.f, q = 0.f;
        int c = tid & 63, gn = n0 + c;
        for (int i = tid; i < 128 * 64; i += 256) {
            int r = i >> 6;
            int gm = m0 + r;
            if (gm < M && gn < N) {
                float v = sC[r * 72 + c] + bias[gn] + addC[(long)gm * ldadd + gn];
                Cb[(long)gm * ldc + gn] = v;
                s += v;
                q += v * v;
            }
        }
        rs[tid] = s;
        rq[tid] = q;
        __syncthreads();
        if (tid < 64 && gn < N) {
            float ts = rs[tid] + rs[tid + 64] + rs[tid + 128] + rs[tid + 192];
            float tq = rq[tid] + rq[tid + 64] + rq[tid + 128] + rq[tid + 192];
            atomicAdd(&bnS[gn], (double)ts);
            atomicAdd(&bnQ[gn], (double)tq);
        }
        return;
    }
    // MODE 0 generic
    for (int i = tid; i < 128 * 64; i += 256) {
        int r = i >> 6, c = i & 63;
        int gm = m0 + r, gn = n0 + c;
        if (gm < M && gn < N) {
            float v = sC[r * 72 + c];
            if (bias) v += bias[gn];
            if (addC) v += addC[(long)gm * ldadd + gn];
            if (act) v = fmaxf(v, 0.f);
            Cb[(long)gm * ldc + gn] = v;
        }
    }
}

// ---------------- 128x48 split-bf16 GEMM with m32n8k16 frags (AGG towers) -----------
// one n-tile (N<=48); fused PNA combine epilogue -> Z planes. blockIdx.z = tower.
#define SBS48 56
#define SB48_PLANE (16 * SBS48)
#define SMEM48_BYTES ((4 * SA_PLANE + 4 * SB48_PLANE) * 2 > 128 * 48 * 4 \
                          ? (4 * SA_PLANE + 4 * SB48_PLANE) * 2 \
                          : 128 * 48 * 4)

__global__ __launch_bounds__(256, 3) void tgemm48_kernel(
    const bf16* __restrict__ Ah, const bf16* __restrict__ Al, int lda, long sAb,
    const bf16* __restrict__ Bh, const bf16* __restrict__ Bl, int ldb, long sBb,
    int M, int K,
    const float* __restrict__ bpost,
    const float* __restrict__ amp, const float* __restrict__ invamp,
    bf16* __restrict__ Zph, bf16* __restrict__ Zpl) {
    extern __shared__ char smem_raw[];
    bf16* bb = (bf16*)smem_raw;
    float* sC = (float*)smem_raw;

    const bf16* Abh = Ah + (long)blockIdx.z * sAb;
    const bf16* Abl = Al + (long)blockIdx.z * sAb;
    const bf16* Bbh = Bh + (long)blockIdx.z * sBb;
    const bf16* Bbl = Bl + (long)blockIdx.z * sBb;
    int m0 = blockIdx.y * 128;
    int tid = threadIdx.x;
    int warp = tid >> 5;
    int wm = (warp & 3) * 32;
    int wn = (warp >> 2) * 24;       // 2 n-groups of 24 cols (3 x n8)
    int numK = (K + 15) / 16;

    const bf16* aSrc[2];
    unsigned aDst[2];
    bool aPred[2];
#pragma unroll
    for (int u = 0; u < 2; u++) {
        int idx = tid + u * 256;
        int pl = idx >> 8, rem = idx & 255;
        int r = rem >> 1, ch = rem & 1;
        const bf16* base = pl ? Abl : Abh;
        aPred[u] = (m0 + r) < M;
        aSrc[u] = base + (long)(m0 + r) * lda + ch * 8;
        aDst[u] = (unsigned)__cvta_generic_to_shared(bb + pl * 2 * SA_PLANE + r * SAS + ch * 8);
    }
    // B: 16 rows x 48 cols x 2 planes; 6 chunks/row -> 192 total; only tid<192 participate.
    // tid>=192 must NOT issue cp.async at all (sz=0 still zero-fills dst -> OOB in R16).
    int bPl = tid >= 96;
    int bRem = bPl ? (tid - 96) : tid;
    int bR = bRem / 6, bCh = bRem % 6;
    bool bAct = tid < 192;
    if (!bAct) { bR = 0; bCh = 0; }   // keep addresses in-bounds even if unused
    const bf16* bBase = bPl ? Bbl : Bbh;
    const bf16* bSrc = bBase + (long)bR * ldb + bCh * 8;
    unsigned bDst = (unsigned)__cvta_generic_to_shared(bb + 4 * SA_PLANE + bPl * 2 * SB48_PLANE +
                                                       bR * SBS48 + bCh * 8);

    auto load_stage = [&](int st, int k0) {
#pragma unroll
        for (int u = 0; u < 2; u++)
            cp16(aDst[u] + st * SA_PLANE * 2, aPred[u] ? (aSrc[u] + k0) : Abh, aPred[u]);
        if (bAct) {
            bool p = (k0 + bR) < K;
            cp16(bDst + st * SB48_PLANE * 2, p ? (bSrc + (long)k0 * ldb) : Bbh, p);
        }
    };

    wmma::fragment<wmma::accumulator, 32, 8, 16, float> acc[3];
#pragma unroll
    for (int j = 0; j < 3; j++) wmma::fill_fragment(acc[j], 0.f);

    load_stage(0, 0);
    CP_COMMIT();

    for (int kt = 0; kt < numK; kt++) {
        int st = kt & 1;
        if (kt + 1 < numK) {
            load_stage(st ^ 1, (kt + 1) * 16);
            CP_COMMIT();
            CP_WAIT1();
        } else {
            CP_WAIT0();
        }
        __syncthreads();

        bf16* sAh = bb + st * SA_PLANE;
        bf16* sAl = bb + 2 * SA_PLANE + st * SA_PLANE;
        bf16* sBh = bb + 4 * SA_PLANE + st * SB48_PLANE;
        bf16* sBl = bb + 4 * SA_PLANE + 2 * SB48_PLANE + st * SB48_PLANE;

        wmma::fragment<wmma::matrix_a, 32, 8, 16, bf16, wmma::row_major> ah, al;
        wmma::fragment<wmma::matrix_b, 32, 8, 16, bf16, wmma::row_major> bh[3], bl[3];
        wmma::load_matrix_sync(ah, &sAh[wm * SAS], SAS);
        wmma::load_matrix_sync(al, &sAl[wm * SAS], SAS);
#pragma unroll
        for (int j = 0; j < 3; j++) {
            wmma::load_matrix_sync(bh[j], &sBh[wn + 8 * j], SBS48);
            wmma::load_matrix_sync(bl[j], &sBl[wn + 8 * j], SBS48);
        }
#pragma unroll
        for (int j = 0; j < 3; j++) {
            wmma::mma_sync(acc[j], al, bh[j], acc[j]);
            wmma::mma_sync(acc[j], ah, bl[j], acc[j]);
            wmma::mma_sync(acc[j], ah, bh[j], acc[j]);
        }
        __syncthreads();
    }

#pragma unroll
    for (int j = 0; j < 3; j++)
        wmma::store_matrix_sync(&sC[wm * 48 + wn + 8 * j], acc[j], 48, wmma::mem_row_major);
    __syncthreads();

    // combine towers + degree scalers -> Z planes; tower = blockIdx.z
    int t = blockIdx.z;
    for (int i = tid; i < 128 * 15; i += 256) {
        int r = i / 15, f = i % 15;
        int gm = m0 + r;
        if (gm < M) {
            const float* row = &sC[r * 48];
            float v = row[f] + amp[gm] * row[15 + f] + invamp[gm] * row[30 + f] +
                      bpost[t * 15 + f];
            long o = (long)gm * 80 + t * 15 + f;
            bsplit(v, &Zph[o], &Zpl[o]);
        }
    }
}

// ---------------- tiny fp32 GEMM for the final MLP ----------------
__global__ void sgemm_s(const float* __restrict__ A, int lda, const float* __restrict__ B,
                        int ldb, float* __restrict__ C, int ldc, int M, int N, int K,
                        const float* __restrict__ bias, int act) {
    int i = blockIdx.x * blockDim.x + threadIdx.x;
    if (i >= M * N) return;
    int m = i / N, n = i % N;
    float s = bias ? bias[n] : 0.f;
    for (int k = 0; k < K; k++) s += A[m * lda + k] * B[k * ldb + n];
    if (act) s = fmaxf(s, 0.f);
    C[m * ldc + n] = s;
}

// ---------------- small utility kernels ----------------
__global__ void zero_i(int* p, int n) {
    int i = blockIdx.x * blockDim.x + threadIdx.x;
    if (i < n) p[i] = 0;
}
__global__ void zero_f(float* p, int n) {
    int i = blockIdx.x * blockDim.x + threadIdx.x;
    if (i < n) p[i] = 0.f;
}
__global__ void zero_bn(double* s, double* q, int n) {
    int i = blockIdx.x * blockDim.x + threadIdx.x;
    if (i < n) { s[i] = 0.0; q[i] = 0.0; }
}
__global__ void zero_zpad(bf16* Zh, bf16* Zl, bf16* Ah, bf16* Al) {
    int i = blockIdx.x * blockDim.x + threadIdx.x;
    if (i < NN * 5) {
        int n = i / 5, k = i % 5;
        Zh[n * 80 + 75 + k] = __float2bfloat16(0.f);
        Zl[n * 80 + 75 + k] = __float2bfloat16(0.f);
    }
    if (i < NN * 20) {
        int n = i / 20, r = i % 20;
        int o = n * 1520 + (r >> 2) * 304 + 300 + (r & 3);
        Ah[o] = __float2bfloat16(0.f);
        Al[o] = __float2bfloat16(0.f);
    }
}

__global__ void hist_k(const int* __restrict__ ei, int* __restrict__ deg) {
    int e = blockIdx.x * blockDim.x + threadIdx.x;
    if (e < NE) atomicAdd(&deg[ei[NE + e]], 1);
}

__global__ void scan_chunks(const int* __restrict__ in, int* __restrict__ out,
                            int* __restrict__ bsum, int n) {
    __shared__ int s[512];
    int b = blockIdx.x, t = threadIdx.x;
    int idx = b * 512 + t;
    int v = (idx < n) ? in[idx] : 0;
    s[t] = v;
    __syncthreads();
    for (int off = 1; off < 512; off <<= 1) {
        int x = (t >= off) ? s[t - off] : 0;
        __syncthreads();
        s[t] += x;
        __syncthreads();
    }
    if (idx < n) out[idx] = s[t] - v;
    if (t == 511) bsum[b] = s[511];
}
__global__ void scan_sums(const int* __restrict__ sums, int* __restrict__ offs, int nb) {
    __shared__ int s[128];
    int t = threadIdx.x;
    int v = (t < nb) ? sums[t] : 0;
    s[t] = v;
    __syncthreads();
    for (int off = 1; off < 128; off <<= 1) {
        int x = (t >= off) ? s[t - off] : 0;
        __syncthreads();
        s[t] += x;
        __syncthreads();
    }
    if (t < nb) offs[t] = s[t] - v;
}
__global__ void scan_add(int* __restrict__ rowptr, const int* __restrict__ offs) {
    int i = blockIdx.x * blockDim.x + threadIdx.x;
    if (i < NN) rowptr[i] += offs[i >> 9];
    if (i == 0) rowptr[NN] = NE;
}

__global__ void fill_csr(const int* __restrict__ ei, const int* __restrict__ ea,
                         const int* __restrict__ rowptr, int* __restrict__ cursor,
                         int* __restrict__ csr) {
    int e = blockIdx.x * blockDim.x + threadIdx.x;
    if (e >= NE) return;
    int d = ei[NE + e];
    int pos = rowptr[d] + atomicAdd(&cursor[d], 1);
    csr[pos] = ei[e] | (ea[e] << 20);
}

__global__ void amp_k(const int* __restrict__ rowptr, float* __restrict__ amp,
                      float* __restrict__ invamp) {
    int i = blockIdx.x * blockDim.x + threadIdx.x;
    if (i >= NN) return;
    int dg = rowptr[i + 1] - rowptr[i];
    float a = logf((float)max(dg, 1) + 1.f) / AVGLOG;
    amp[i] = a;
    invamp[i] = 1.f / a;
}

__global__ void embed_k(const int* __restrict__ x, const float* __restrict__ emb,
                        bf16* __restrict__ Hh, bf16* __restrict__ Hl) {
    int i = blockIdx.x * blockDim.x + threadIdx.x;
    if (i >= NN * 80) return;
    int n = i / 80, f = i % 80;
    float v = (f < 75) ? emb[x[n] * 75 + f] : 0.f;
    bsplit(v, &Hh[i], &Hl[i]);
}

// ---------------- weight prep (bf16 planes) ----------------
__global__ void prep_wcat(const float* __restrict__ Wpre, bf16* __restrict__ Wh,
                          bf16* __restrict__ Wl) {
    int i = blockIdx.x * blockDim.x + threadIdx.x;
    if (i >= NL * 75 * 832) return;
    int l = i / (75 * 832), r = i % (75 * 832);
    int k = r / 832, j = r % 832;
    if (j >= 750 && j < 825) return;
    float v = 0.f;
    if (j < 750) {
        int part = j / 375, j2 = j % 375;
        int t = j2 / 75, f = j2 % 75;
        int c = part * 75 + k;
        v = Wpre[((l * TW + t) * 225 + c) * 75 + f];
    }
    bsplit(v, &Wh[(l * 75 + k) * 832 + j], &Wl[(l * 75 + k) * 832 + j]);
}

__global__ void prep_w0(const float* __restrict__ Wpost, const float* __restrict__ Wlin,
                        bf16* __restrict__ Wh, bf16* __restrict__ Wl) {
    int i = blockIdx.x * blockDim.x + threadIdx.x;
    if (i >= NL * 75 * 75) return;
    int l = i / 5625, r = i % 5625;
    int k = r / 75, c = r % 75;
    float s = 0.f;
    for (int d = 0; d < 75; d++) {
        int t = d / 15, f = d % 15;
        s += Wpost[((l * TW + t) * 975 + k) * 15 + f] * Wlin[l * 5625 + d * 75 + c];
    }
    int o = (l * 75 + k) * 832 + 750 + c;
    bsplit(s, &Wh[o], &Wl[o]);
}

__global__ void prep_etab(const float* __restrict__ edge_emb, const float* __restrict__ We,
                          const float* __restrict__ be, const float* __restrict__ Wpre,
                          const float* __restrict__ bpre, float* __restrict__ Etab) {
    int a = blockIdx.x, l = blockIdx.y;
    __shared__ float ev[75];
    int t0 = threadIdx.x;
    if (t0 < 75) {
        float s = be[l * 75 + t0];
        for (int c = 0; c < 50; c++) s += edge_emb[a * 50 + c] * We[(l * 50 + c) * 75 + t0];
        ev[t0] = s;
    }
    __syncthreads();
    for (int j = t0; j < 375; j += blockDim.x) {
        int t = j / 75, f = j % 75;
        float s = bpre[(l * TW + t) * 75 + f];
        for (int d = 0; d < 75; d++)
            s += ev[d] * Wpre[((l * TW + t) * 225 + 150 + d) * 75 + f];
        Etab[(l * 4 + a) * 375 + j] = s;
    }
}

__global__ void prep_wg(const float* __restrict__ Wpost, bf16* __restrict__ Wh,
                        bf16* __restrict__ Wl) {
    int i = blockIdx.x * blockDim.x + threadIdx.x;
    if (i >= NL * TW * 300 * 48) return;
    int lt = i / (300 * 48), r = i % (300 * 48);
    int c = r / 48, col = r % 48;
    float v = 0.f;
    if (col < 45) {
        int g = col / 15, f = col % 15;
        v = Wpost[(lt * 975 + 75 + g * 300 + c) * 15 + f];
    }
    int o = (lt * 300 + c) * 48 + col;
    bsplit(v, &Wh[o], &Wl[o]);
}

__global__ void prep_wlin(const float* __restrict__ Wlin, bf16* __restrict__ Wh,
                          bf16* __restrict__ Wl) {
    int i = blockIdx.x * blockDim.x + threadIdx.x;
    if (i >= NL * 75 * 80) return;
    int l = i / (75 * 80), r = i % (75 * 80);
    int k = r / 80, c = r % 80;
    float v = (c < 75) ? Wlin[l * 5625 + k * 75 + c] : 0.f;
    int o = (l * 75 + k) * 80 + c;
    bsplit(v, &Wh[o], &Wl[o]);
}

// ---------------- PNA aggregation: writes AGG hi/lo planes [N][T][304] --------------
__global__ __launch_bounds__(384) void pna_agg(const float* __restrict__ CAB,
                                               const float* __restrict__ Etab,
                                               const int* __restrict__ rowptr,
                                               const int* __restrict__ csr,
                                               bf16* __restrict__ AGGh,
                                               bf16* __restrict__ AGGl) {
    int n = blockIdx.x;
    int j = threadIdx.x;
    if (j >= 375) return;
    float adst = CAB[(long)n * CLD + j];
    int beg = rowptr[n], end = rowptr[n + 1];
    float s = 0.f, sq = 0.f, mn = 3.4e38f, mx = -3.4e38f;
    int e = beg;
    for (; e + 1 < end; e += 2) {
        int p0 = csr[e], p1 = csr[e + 1];
        float b0 = CAB[(long)(p0 & 0xFFFFF) * CLD + 375 + j];
        float b1 = CAB[(long)(p1 & 0xFFFFF) * CLD + 375 + j];
        float v0 = adst + b0 + Etab[(p0 >> 20) * 375 + j];
        float v1 = adst + b1 + Etab[(p1 >> 20) * 375 + j];
        s += v0 + v1;
        sq += v0 * v0 + v1 * v1;
        mn = fminf(mn, fminf(v0, v1));
        mx = fmaxf(mx, fmaxf(v0, v1));
    }
    if (e < end) {
        int p0 = csr[e];
        float v0 = adst + CAB[(long)(p0 & 0xFFFFF) * CLD + 375 + j] + Etab[(p0 >> 20) * 375 + j];
        s += v0;
        sq += v0 * v0;
        mn = fminf(mn, v0);
        mx = fmaxf(mx, v0);
    }
    int dg = end - beg;
    float denom = fmaxf((float)dg, 1.f);
    float mean = s / denom, msq = sq / denom;
    float sd = sqrtf(fmaxf(msq - mean * mean, 0.f) + 1e-5f);
    if (dg == 0) { mn = 0.f; mx = 0.f; }
    int t = j / 75, f = j % 75;
    long o = (long)n * 1520 + t * 304;
    bsplit(mean, &AGGh[o + f], &AGGl[o + f]);
    bsplit(mn, &AGGh[o + 75 + f], &AGGl[o + 75 + f]);
    bsplit(mx, &AGGh[o + 150 + f], &AGGl[o + 150 + f]);
    bsplit(sd, &AGGh[o + 225 + f], &AGGl[o + 225 + f]);
}

// ---------------- BN apply + ReLU -> H hi/lo planes ----------------
__global__ void bn_apply(const float* __restrict__ Y, const double* __restrict__ S,
                         const double* __restrict__ Q, const float* __restrict__ gamma,
                         const float* __restrict__ beta, bf16* __restrict__ Hh,
                         bf16* __restrict__ Hl) {
    int i = blockIdx.x * blockDim.x + threadIdx.x;
    if (i >= NN * 80) return;
    int n = i / 80, f = i % 80;
    float v = 0.f;
    if (f < 75) {
        double mu = S[f] / (double)NN;
        double var = Q[f] / (double)NN - mu * mu;
        float inv = rsqrtf((float)var + 1e-5f);
        v = gamma[f] * ((Y[(long)n * DD + f] - (float)mu) * inv) + beta[f];
        v = fmaxf(v, 0.f);
    }
    bsplit(v, &Hh[i], &Hl[i]);
}

// ---------------- pooling ----------------
__global__ void pool_k(const int* __restrict__ batch, const bf16* __restrict__ Hh,
                       const bf16* __restrict__ Hl, float* __restrict__ pool) {
    int i = blockIdx.x * blockDim.x + threadIdx.x;
    if (i >= NN * DD) return;
    int n = i / DD, f = i % DD;
    float v = __bfloat162float(Hh[n * 80 + f]) + __bfloat162float(Hl[n * 80 + f]);
    atomicAdd(&pool[batch[n] * DD + f], v);
}

// ---------------- launch ----------------
template <int MODE>
static inline void tgemm(const bf16* Ah, const bf16* Al, int lda, long sA, const bf16* Bh,
                         const bf16* Bl, int ldb, long sB, float* C, int ldc, long sC, int M,
                         int N, int K, const float* bias, const float* addC, int ldadd,
                         double* bnS, double* bnQ, int act, int nz) {
    dim3 grid((N + 63) / 64, (M + 127) / 128, nz);
    tgemm_kernel<MODE><<<grid, 256, SMEM_BYTES>>>(Ah, Al, lda, sA, Bh, Bl, ldb, sB, C, ldc, sC,
                                                  M, N, K, bias, addC, ldadd, bnS, bnQ, act);
}

extern "C" void kernel_launch(void* const* d_in, const int* in_sizes, int n_in,
                              void* d_out, int out_size) {
    const int* x = (const int*)d_in[0];
    const int* ei = (const int*)d_in[1];
    const int* ea = (const int*)d_in[2];
    const int* batch = (const int*)d_in[3];
    const float* node_emb = (const float*)d_in[4];
    const float* edge_emb = (const float*)d_in[5];
    const float* We = (const float*)d_in[6];
    const float* be = (const float*)d_in[7];
    const float* Wpre = (const float*)d_in[8];
    const float* bpre = (const float*)d_in[9];
    const float* Wpost = (const float*)d_in[10];
    const float* bpost = (const float*)d_in[11];
    const float* Wlin = (const float*)d_in[12];
    const float* blin = (const float*)d_in[13];
    const float* gamma = (const float*)d_in[14];
    const float* beta = (const float*)d_in[15];
    const float* W1 = (const float*)d_in[16];
    const float* b1 = (const float*)d_in[17];
    const float* W2 = (const float*)d_in[18];
    const float* b2 = (const float*)d_in[19];
    const float* W3 = (const float*)d_in[20];
    const float* b3 = (const float*)d_in[21];
    float* out = (float*)d_out;

    cudaFuncSetAttribute(tgemm_kernel<0>, cudaFuncAttributeMaxDynamicSharedMemorySize,
                         SMEM_BYTES);
    cudaFuncSetAttribute(tgemm_kernel<2>, cudaFuncAttributeMaxDynamicSharedMemorySize,
                         SMEM_BYTES);
    cudaFuncSetAttribute(tgemm48_kernel, cudaFuncAttributeMaxDynamicSharedMemorySize,
                         SMEM48_BYTES);

    bf16 *Hh, *Hl, *AGGh, *AGGl, *Zh, *Zl, *Wcath, *Wcatl, *WGh, *WGl, *Wlinh, *Wlinl;
    float *CAB, *Y, *amp, *invamp, *Etab, *pool, *z1, *z2;
    int *deg, *rowptr, *csr, *bsum, *boffs;
    double *bnS, *bnQ;
    cudaGetSymbolAddress((void**)&Hh, g_Hh);
    cudaGetSymbolAddress((void**)&Hl, g_Hl);
    cudaGetSymbolAddress((void**)&CAB, g_CAB);
    cudaGetSymbolAddress((void**)&AGGh, g_AGGh);
    cudaGetSymbolAddress((void**)&AGGl, g_AGGl);
    cudaGetSymbolAddress((void**)&Zh, g_Zh);
    cudaGetSymbolAddress((void**)&Zl, g_Zl);
    cudaGetSymbolAddress((void**)&Y, g_Y);
    cudaGetSymbolAddress((void**)&amp, g_amp);
    cudaGetSymbolAddress((void**)&invamp, g_invamp);
    cudaGetSymbolAddress((void**)&deg, g_deg);
    cudaGetSymbolAddress((void**)&rowptr, g_rowptr);
    cudaGetSymbolAddress((void**)&csr, g_csr);
    cudaGetSymbolAddress((void**)&bsum, g_bsum);
    cudaGetSymbolAddress((void**)&boffs, g_boffs);
    cudaGetSymbolAddress((void**)&Wcath, g_Wcath);
    cudaGetSymbolAddress((void**)&Wcatl, g_Wcatl);
    cudaGetSymbolAddress((void**)&Etab, g_Etab);
    cudaGetSymbolAddress((void**)&WGh, g_WGh);
    cudaGetSymbolAddress((void**)&WGl, g_WGl);
    cudaGetSymbolAddress((void**)&Wlinh, g_Wlinh);
    cudaGetSymbolAddress((void**)&Wlinl, g_Wlinl);
    cudaGetSymbolAddress((void**)&bnS, g_bnS);
    cudaGetSymbolAddress((void**)&bnQ, g_bnQ);
    cudaGetSymbolAddress((void**)&pool, g_pool);
    cudaGetSymbolAddress((void**)&z1, g_z1);
    cudaGetSymbolAddress((void**)&z2, g_z2);
    int* cursor = deg + NN;

    // ---- launch index 3 = layer-0 CAB GEMM (ncu capture slot) ----
    embed_k<<<(NN * 80 + 255) / 256, 256>>>(x, node_emb, Hh, Hl);               // 0
    prep_wcat<<<(NL * 75 * 832 + 255) / 256, 256>>>(Wpre, Wcath, Wcatl);        // 1
    prep_w0<<<(NL * 75 * 75 + 255) / 256, 256>>>(Wpost, Wlin, Wcath, Wcatl);    // 2
    tgemm<0>(Hh, Hl, 80, 0, Wcath, Wcatl, 832, 0, CAB, CLD, 0, NN, 825, 75,     // 3
             nullptr, nullptr, 0, nullptr, nullptr, 0, 1);
    prep_wg<<<(NL * TW * 300 * 48 + 255) / 256, 256>>>(Wpost, WGh, WGl);        // 4
    prep_wlin<<<(NL * 75 * 80 + 255) / 256, 256>>>(Wlin, Wlinh, Wlinl);         // 5
    zero_zpad<<<(NN * 20 + 255) / 256, 256>>>(Zh, Zl, AGGh, AGGl);              // 6
    zero_bn<<<(NL * DD + 255) / 256, 256>>>(bnS, bnQ, NL * DD);                 // 7

    // ---- graph structure prep ----
    zero_i<<<(2 * NN + 255) / 256, 256>>>(deg, 2 * NN);
    hist_k<<<(NE + 255) / 256, 256>>>(ei, deg);
    int nchunks = (NN + 511) / 512;
    scan_chunks<<<nchunks, 512>>>(deg, rowptr, bsum, NN);
    scan_sums<<<1, 128>>>(bsum, boffs, nchunks);
    scan_add<<<(NN + 255) / 256, 256>>>(rowptr, boffs);
    fill_csr<<<(NE + 255) / 256, 256>>>(ei, ea, rowptr, cursor, csr);
    amp_k<<<(NN + 255) / 256, 256>>>(rowptr, amp, invamp);
    prep_etab<<<dim3(4, NL), 384>>>(edge_emb, We, be, Wpre, bpre, Etab);

    // ---- layers ----
    for (int l = 0; l < NL; l++) {
        if (l > 0) {
            tgemm<0>(Hh, Hl, 80, 0, Wcath + l * 75 * 832, Wcatl + l * 75 * 832, 832, 0, CAB,
                     CLD, 0, NN, 825, 75, nullptr, nullptr, 0, nullptr, nullptr, 0, 1);
        }
        pna_agg<<<NN, 384>>>(CAB, Etab + l * 4 * 375, rowptr, csr, AGGh, AGGl);
        // AGG GEMM (128x48 tiles) + fused combine -> Z planes
        {
            dim3 grid48(1, (NN + 127) / 128, TW);
            tgemm48_kernel<<<grid48, 256, SMEM48_BYTES>>>(
                AGGh, AGGl, 1520, 304, WGh + l * TW * 300 * 48, WGl + l * TW * 300 * 48, 48,
                (long)300 * 48, NN, 300, bpost + l * TW * FO, amp, invamp, Zh, Zl);
        }
        // Y GEMM + fused BN stats
        tgemm<2>(Zh, Zl, 80, 0, Wlinh + l * 75 * 80, Wlinl + l * 75 * 80, 80, 0, Y, 75, 0, NN,
                 75, 75, blin + l * 75, CAB + 750, CLD, bnS + l * DD, bnQ + l * DD, 0, 1);
        bn_apply<<<(NN * 80 + 255) / 256, 256>>>(Y, bnS + l * DD, bnQ + l * DD, gamma + l * DD,
                                                 beta + l * DD, Hh, Hl);
    }

    // ---- pooling + MLP (tiny, fp32 SIMT) ----
    zero_f<<<(NG * DD + 255) / 256, 256>>>(pool, NG * DD);
    pool_k<<<(NN * DD + 255) / 256, 256>>>(batch, Hh, Hl, pool);
    sgemm_s<<<(NG * 50 + 255) / 256, 256>>>(pool, 75, W1, 50, z1, 50, NG, 50, 75, b1, 1);
    sgemm_s<<<(NG * 25 + 255) / 256, 256>>>(z1, 50, W2, 25, z2, 25, NG, 25, 50, b2, 1);
    sgemm_s<<<(NG * 1 + 255) / 256, 256>>>(z2, 25, W3, 1, out, 1, NG, 1, 25, b3, 0);
}